// round 9
// baseline (speedup 1.0000x reference)
#include <cuda_runtime.h>
#include <math.h>
#include <stdint.h>
#include <stddef.h>

#define D_DIM   512
#define KD      128
#define VD      128
#define VOCAB   10001
#define BATCH   64
#define TDEC    192
#define TENC    512
#define NTHR    512
#define LPLD    10016          // padded row stride for logits partials
#define LKS     4              // logits K-split

// ---------------------------------------------------------------------------
// Persistent state / scratch (device globals; no allocation allowed)
// ---------------------------------------------------------------------------
__device__ __align__(16) float g_h1[BATCH * D_DIM], g_c1[BATCH * D_DIM];
__device__ __align__(16) float g_h2[BATCH * D_DIM], g_c2[BATCH * D_DIM];
__device__ __align__(16) float g_h3[BATCH * D_DIM], g_c3[BATCH * D_DIM];
__device__ __align__(16) float g_ctx[BATCH * VD];
__device__ __align__(16) float g_hid[BATCH * D_DIM];
__device__ __align__(16) float g_Gp[16 * BATCH * 2048];   // LSTM gate partials (interleaved n)
__device__ __align__(16) float g_Pp[20 * BATCH * D_DIM];  // p1 partials
__device__ __align__(16) float g_Lp[LKS * BATCH * LPLD];  // logits partials
__device__ __align__(16) float g_attn_scratch[BATCH * TENC];
__device__ __align__(16) float g_gen_scratch [TDEC * BATCH];
__device__ unsigned g_cntG[16];            // per-n-tile split counters (LSTM)
__device__ unsigned g_bar_count, g_bar_gen;

struct KP {
    const int*   inputs;
    const float* keys;   const float* values; const int* ulen;
    const float* emb;
    const float* w_ih0; const float* w_hh0; const float* b_ih0; const float* b_hh0;
    const float* w_ih1; const float* w_hh1; const float* b_ih1; const float* b_hh1;
    const float* w_ih2; const float* w_hh2; const float* b_ih2; const float* b_hh2;
    const float* q_w;  const float* q_b;
    const float* p1_w; const float* p1_b; const float* p2_b;
    float* out_logits; float* out_attn; float* out_gen;
};

struct __align__(16) Smem {
    union {
        struct { float As[32][64]; float Bs[32][128]; } g;          // FFMA gemm: 24KB
        struct { float As[32][72]; float Bh[32][136]; float Bl[32][136]; } t;  // mma: 43KB
        struct { float h3s[D_DIM]; float q[KD]; float arr[TENC];
                 float red[NTHR]; float ps[4][VD]; } a;
        struct { float sv[NTHR]; int si[NTHR]; } s;
    } u;
    int flag;
};

// ---------------------------------------------------------------------------
// tf32 helpers (mma.sync + split)
// ---------------------------------------------------------------------------
__device__ __forceinline__ unsigned cvt_tf32(float x)
{
    unsigned r;
    asm("cvt.rna.tf32.f32 %0, %1;" : "=r"(r) : "f"(x));
    return r;
}
__device__ __forceinline__ void split_tf32(float x, unsigned& hi, unsigned& lo)
{
    hi = cvt_tf32(x);
    lo = cvt_tf32(x - __uint_as_float(hi));
}
__device__ __forceinline__ void mma_tf32(float& d0, float& d1, float& d2, float& d3,
                                         unsigned a0, unsigned a1, unsigned a2, unsigned a3,
                                         unsigned b0, unsigned b1)
{
    asm("mma.sync.aligned.m16n8k8.row.col.f32.tf32.tf32.f32 "
        "{%0,%1,%2,%3}, {%4,%5,%6,%7}, {%8,%9}, {%0,%1,%2,%3};"
        : "+f"(d0), "+f"(d1), "+f"(d2), "+f"(d3)
        : "r"(a0), "r"(a1), "r"(a2), "r"(a3), "r"(b0), "r"(b1));
}

// ---------------------------------------------------------------------------
// Grid barrier (R4 atomic version — measured fastest)
// ---------------------------------------------------------------------------
__device__ __forceinline__ void grid_sync()
{
    __syncthreads();
    if (threadIdx.x == 0) {
        __threadfence();
        unsigned my = *((volatile unsigned*)&g_bar_gen);
        if (atomicAdd(&g_bar_count, 1u) == gridDim.x - 1) {
            atomicExch(&g_bar_count, 0u);
            __threadfence();
            atomicAdd(&g_bar_gen, 1u);
        } else {
            while (*((volatile unsigned*)&g_bar_gen) == my) { }
        }
        __threadfence();
    }
    __syncthreads();
}

// ---------------------------------------------------------------------------
// Virtual-operand loaders.  Mutable state via __ldcg (L2-coherent).
// ---------------------------------------------------------------------------
__device__ __forceinline__ float4 ld4(const float* p) { return *reinterpret_cast<const float4*>(p); }
__device__ __forceinline__ float4 ldcg4(const float* p) { return __ldcg(reinterpret_cast<const float4*>(p)); }

template<int MODE>
__device__ __forceinline__ float4 loadA(const KP& p, int tok, int m, int k)
{
    if (MODE == 0) {
        if (k < 512)      return ld4(p.emb + (size_t)tok * D_DIM + k);
        else if (k < 640) return ldcg4(g_ctx + m * VD + (k - 512));
        else              return ldcg4(g_h1 + m * D_DIM + (k - 640));
    } else if (MODE == 1) {
        return (k < 512) ? ldcg4(g_h1 + m * D_DIM + k) : ldcg4(g_h2 + m * D_DIM + (k - 512));
    } else if (MODE == 2) {
        return (k < 512) ? ldcg4(g_h2 + m * D_DIM + k) : ldcg4(g_h3 + m * D_DIM + (k - 512));
    } else {
        return (k < 512) ? ldcg4(g_h3 + m * D_DIM + k) : ldcg4(g_ctx + m * VD + (k - 512));
    }
}

// LSTM modes use gate-interleaved virtual columns: n -> phys row (n&3)*512 + (n>>2)
template<int MODE>
__device__ __forceinline__ float4 loadB(const KP& p, int n, int k)
{
    if (MODE <= 2) {
        int row = (n & 3) * 512 + (n >> 2);
        if (MODE == 0) return (k < 640) ? ld4(p.w_ih0 + (size_t)row * 640 + k)
                                        : ld4(p.w_hh0 + (size_t)row * 512 + (k - 640));
        if (MODE == 1) return (k < 512) ? ld4(p.w_ih1 + (size_t)row * 512 + k)
                                        : ld4(p.w_hh1 + (size_t)row * 512 + (k - 512));
        return (k < 512) ? ld4(p.w_ih2 + (size_t)row * 512 + k)
                         : ld4(p.w_hh2 + (size_t)row * 512 + (k - 512));
    }
    return ld4(p.p1_w + (size_t)n * 640 + k);
}

// ---------------------------------------------------------------------------
// LSTM cell combine (last-arriving split block; deterministic ss order)
// Tile nt covers units u0..u0+31 (all gates). 2048 (m,u) pairs / 512 thr = 4.
// ---------------------------------------------------------------------------
template<int MODE, int KSPLIT>
__device__ void lstm_combine(const KP& p, int nt)
{
    const int tid = threadIdx.x;
    const float* bih = (MODE == 0) ? p.b_ih0 : (MODE == 1) ? p.b_ih1 : p.b_ih2;
    const float* bhh = (MODE == 0) ? p.b_hh0 : (MODE == 1) ? p.b_hh1 : p.b_hh2;
    float* c = (MODE == 0) ? g_c1 : (MODE == 1) ? g_c2 : g_c3;
    float* h = (MODE == 0) ? g_h1 : (MODE == 1) ? g_h2 : g_h3;
    const int u0 = nt * 32;
#pragma unroll
    for (int j = 0; j < 4; j++) {
        int pair = tid + j * NTHR;
        int m = pair >> 5, u = u0 + (pair & 31);
        float4 s = make_float4(0.f, 0.f, 0.f, 0.f);
#pragma unroll
        for (int ss = 0; ss < KSPLIT; ss++) {
            float4 v = ldcg4(&g_Gp[((size_t)(ss * BATCH + m)) * 2048 + u * 4]);
            s.x += v.x; s.y += v.y; s.z += v.z; s.w += v.w;
        }
        float gi = s.x + bih[u]        + bhh[u];
        float gf = s.y + bih[512 + u]  + bhh[512 + u];
        float gg = s.z + bih[1024 + u] + bhh[1024 + u];
        float go = s.w + bih[1536 + u] + bhh[1536 + u];
        float si = 1.f / (1.f + expf(-gi));
        float sf = 1.f / (1.f + expf(-gf));
        float so = 1.f / (1.f + expf(-go));
        float cc = sf * __ldcg(&c[m * D_DIM + u]) + si * tanhf(gg);
        c[m * D_DIM + u] = cc;
        h[m * D_DIM + u] = so * tanhf(cc);
    }
}

// ---------------------------------------------------------------------------
// FFMA GEMM (modes 0-3): 64x128 tile, 512 threads, 4x4 thread-tile.
// ---------------------------------------------------------------------------
template<int MODE, int NT, int KSPLIT, int KC, int NCH, bool EXCL, bool CELL>
__device__ void gemm_phase(const KP& p, Smem& sm, int step, float* out)
{
    constexpr int NTILES = NT * KSPLIT;
    const int tid = threadIdx.x;
    const int ty = tid >> 5, tx = tid & 31;
    const int arow = tid & 63;
    const int akg  = (tid >> 6) * 4;
    const int brow = tid & 127;
    const int bkg  = (tid >> 7) * 4;

    int bid = blockIdx.x, stride = gridDim.x;
    if (EXCL) { if (bid < 64) return; bid -= 64; stride -= 64; }

    int tok = 0;
    if (MODE == 0) tok = p.inputs[step * BATCH + arow];

    for (int tile = bid; tile < NTILES; tile += stride) {
        const int nt = tile % NT, ks = tile / NT;
        const int n0 = nt * 128, kb = ks * KC;
        float acc[4][4] = {};

        float4 rA  = loadA<MODE>(p, tok, arow, kb + akg);
        float4 rB0 = loadB<MODE>(p, n0 + brow, kb + bkg);
        float4 rB1 = loadB<MODE>(p, n0 + brow, kb + bkg + 16);

#pragma unroll 1
        for (int ch = 0; ch < NCH; ch++) {
            __syncthreads();
            sm.u.g.As[akg + 0][arow] = rA.x;  sm.u.g.As[akg + 1][arow] = rA.y;
            sm.u.g.As[akg + 2][arow] = rA.z;  sm.u.g.As[akg + 3][arow] = rA.w;
            sm.u.g.Bs[bkg + 0][brow] = rB0.x; sm.u.g.Bs[bkg + 1][brow] = rB0.y;
            sm.u.g.Bs[bkg + 2][brow] = rB0.z; sm.u.g.Bs[bkg + 3][brow] = rB0.w;
            sm.u.g.Bs[bkg + 16][brow] = rB1.x; sm.u.g.Bs[bkg + 17][brow] = rB1.y;
            sm.u.g.Bs[bkg + 18][brow] = rB1.z; sm.u.g.Bs[bkg + 19][brow] = rB1.w;
            __syncthreads();
            if (ch + 1 < NCH) {
                int k2 = kb + (ch + 1) * 32;
                rA  = loadA<MODE>(p, tok, arow, k2 + akg);
                rB0 = loadB<MODE>(p, n0 + brow, k2 + bkg);
                rB1 = loadB<MODE>(p, n0 + brow, k2 + bkg + 16);
            }
#pragma unroll 8
            for (int kk = 0; kk < 32; kk++) {
                float4 a4 = *reinterpret_cast<const float4*>(&sm.u.g.As[kk][ty * 4]);
                float4 b4 = *reinterpret_cast<const float4*>(&sm.u.g.Bs[kk][tx * 4]);
                acc[0][0] = fmaf(a4.x, b4.x, acc[0][0]);
                acc[0][1] = fmaf(a4.x, b4.y, acc[0][1]);
                acc[0][2] = fmaf(a4.x, b4.z, acc[0][2]);
                acc[0][3] = fmaf(a4.x, b4.w, acc[0][3]);
                acc[1][0] = fmaf(a4.y, b4.x, acc[1][0]);
                acc[1][1] = fmaf(a4.y, b4.y, acc[1][1]);
                acc[1][2] = fmaf(a4.y, b4.z, acc[1][2]);
                acc[1][3] = fmaf(a4.y, b4.w, acc[1][3]);
                acc[2][0] = fmaf(a4.z, b4.x, acc[2][0]);
                acc[2][1] = fmaf(a4.z, b4.y, acc[2][1]);
                acc[2][2] = fmaf(a4.z, b4.z, acc[2][2]);
                acc[2][3] = fmaf(a4.z, b4.w, acc[2][3]);
                acc[3][0] = fmaf(a4.w, b4.x, acc[3][0]);
                acc[3][1] = fmaf(a4.w, b4.y, acc[3][1]);
                acc[3][2] = fmaf(a4.w, b4.z, acc[3][2]);
                acc[3][3] = fmaf(a4.w, b4.w, acc[3][3]);
            }
        }

        const int NNout = (MODE == 3) ? 512 : 2048;
#pragma unroll
        for (int i = 0; i < 4; i++)
            *reinterpret_cast<float4*>(
                &out[((size_t)(ks * BATCH + ty * 4 + i)) * NNout + n0 + tx * 4]) =
                make_float4(acc[i][0], acc[i][1], acc[i][2], acc[i][3]);

        if (CELL) {
            __syncthreads();
            if (tid == 0) {
                __threadfence();
                sm.flag = (atomicAdd(&g_cntG[nt], 1u) == KSPLIT - 1);
            }
            __syncthreads();
            if (sm.flag) {
                __threadfence();
                lstm_combine<MODE, KSPLIT>(p, nt);
                if (tid == 0) g_cntG[nt] = 0;
            }
        }
    }
}

// ---------------------------------------------------------------------------
// Logits GEMM via tf32x3 mma.sync: C = hid(64x512) @ emb^T, tiles 64x128.
// 16 warps = 4m x 4n; warp = m16 x n32; K chunks of 32 staged in smem.
// ---------------------------------------------------------------------------
template<int NT>
__device__ void logits_mma_phase(const KP& p, Smem& sm, float* out)
{
    constexpr int KC = 512 / LKS;          // 128
    constexpr int NTILES = NT * LKS;       // 316
    const int tid = threadIdx.x;
    const int warp = tid >> 5, lane = tid & 31;
    const int wm = warp >> 2, wn = warp & 3;
    const int g = lane >> 2, t = lane & 3;

    const int am  = tid & 63;              // A staging m
    const int akq = (tid >> 6) * 4;        // A staging k group (4)
    const int bn  = tid & 127;             // B staging local n
    const int bkq = (tid >> 7) * 8;        // B staging k group (8)

    for (int tile = blockIdx.x; tile < NTILES; tile += gridDim.x) {
        const int nt = tile % NT, ks = tile / NT;
        const int n0 = nt * 128, kb = ks * KC;
        float acc[4][4] = {};              // [n-subtile][frag]

#pragma unroll 1
        for (int ch = 0; ch < KC / 32; ch++) {
            const int k0 = kb + ch * 32;
            float4 av = ldcg4(&g_hid[am * D_DIM + k0 + akq]);
            const int gn = n0 + bn;
            float4 bv0 = make_float4(0.f, 0.f, 0.f, 0.f);
            float4 bv1 = make_float4(0.f, 0.f, 0.f, 0.f);
            if (gn < VOCAB) {
                bv0 = ld4(p.emb + (size_t)gn * D_DIM + k0 + bkq);
                bv1 = ld4(p.emb + (size_t)gn * D_DIM + k0 + bkq + 4);
            }
            __syncthreads();
            sm.u.t.As[akq + 0][am] = av.x; sm.u.t.As[akq + 1][am] = av.y;
            sm.u.t.As[akq + 2][am] = av.z; sm.u.t.As[akq + 3][am] = av.w;
            float bvals[8] = {bv0.x, bv0.y, bv0.z, bv0.w, bv1.x, bv1.y, bv1.z, bv1.w};
#pragma unroll
            for (int i = 0; i < 8; i++) {
                unsigned hi, lo;
                split_tf32(bvals[i], hi, lo);
                sm.u.t.Bh[bkq + i][bn] = __uint_as_float(hi);
                sm.u.t.Bl[bkq + i][bn] = __uint_as_float(lo);
            }
            __syncthreads();

#pragma unroll
            for (int kk = 0; kk < 32; kk += 8) {
                float fa0 = sm.u.t.As[kk + t][wm * 16 + g];
                float fa1 = sm.u.t.As[kk + t][wm * 16 + g + 8];
                float fa2 = sm.u.t.As[kk + t + 4][wm * 16 + g];
                float fa3 = sm.u.t.As[kk + t + 4][wm * 16 + g + 8];
                unsigned ah0, al0, ah1, al1, ah2, al2, ah3, al3;
                split_tf32(fa0, ah0, al0); split_tf32(fa1, ah1, al1);
                split_tf32(fa2, ah2, al2); split_tf32(fa3, ah3, al3);
#pragma unroll
                for (int s = 0; s < 4; s++) {
                    const int nn = wn * 32 + s * 8 + g;
                    unsigned bh0 = __float_as_uint(sm.u.t.Bh[kk + t][nn]);
                    unsigned bh1 = __float_as_uint(sm.u.t.Bh[kk + t + 4][nn]);
                    unsigned bl0 = __float_as_uint(sm.u.t.Bl[kk + t][nn]);
                    unsigned bl1 = __float_as_uint(sm.u.t.Bl[kk + t + 4][nn]);
                    mma_tf32(acc[s][0], acc[s][1], acc[s][2], acc[s][3],
                             ah0, ah1, ah2, ah3, bh0, bh1);
                    mma_tf32(acc[s][0], acc[s][1], acc[s][2], acc[s][3],
                             ah0, ah1, ah2, ah3, bl0, bl1);
                    mma_tf32(acc[s][0], acc[s][1], acc[s][2], acc[s][3],
                             al0, al1, al2, al3, bh0, bh1);
                }
            }
        }

        // epilogue: C frag (row m, cols 2t/2t+1) -> g_Lp[ks][m][n]
#pragma unroll
        for (int s = 0; s < 4; s++) {
            const int nb = n0 + wn * 32 + s * 8 + 2 * t;
            const int m0 = wm * 16 + g;
            if (nb + 1 < VOCAB) {
                *reinterpret_cast<float2*>(&out[((size_t)(ks * BATCH + m0)) * LPLD + nb]) =
                    make_float2(acc[s][0], acc[s][1]);
                *reinterpret_cast<float2*>(&out[((size_t)(ks * BATCH + m0 + 8)) * LPLD + nb]) =
                    make_float2(acc[s][2], acc[s][3]);
            } else {
                if (nb < VOCAB) {
                    out[((size_t)(ks * BATCH + m0)) * LPLD + nb] = acc[s][0];
                    out[((size_t)(ks * BATCH + m0 + 8)) * LPLD + nb] = acc[s][2];
                }
                if (nb + 1 < VOCAB) {
                    out[((size_t)(ks * BATCH + m0)) * LPLD + nb + 1] = acc[s][1];
                    out[((size_t)(ks * BATCH + m0 + 8)) * LPLD + nb + 1] = acc[s][3];
                }
            }
        }
    }
}

// ---------------------------------------------------------------------------
// Query + attention + context.  One block per batch element (blocks 0..63).
// ---------------------------------------------------------------------------
__device__ void attn_phase(const KP& p, Smem& sm, bool with_q, float* attn_out)
{
    if (blockIdx.x >= BATCH) return;
    const int b = blockIdx.x, tid = threadIdx.x;

    if (with_q) {
        sm.u.a.h3s[tid] = __ldcg(&g_h3[b * D_DIM + tid]);
        __syncthreads();
        {
            int n = tid >> 2, part = tid & 3;
            const float4* wp = reinterpret_cast<const float4*>(p.q_w + (size_t)n * D_DIM + part * 128);
            const float4* hp = reinterpret_cast<const float4*>(sm.u.a.h3s + part * 128);
            float s = 0.f;
#pragma unroll
            for (int i = 0; i < 32; i++) {
                float4 wv = wp[i], hv = hp[i];
                s = fmaf(wv.x, hv.x, s); s = fmaf(wv.y, hv.y, s);
                s = fmaf(wv.z, hv.z, s); s = fmaf(wv.w, hv.w, s);
            }
            s += __shfl_down_sync(0xffffffffu, s, 1);
            s += __shfl_down_sync(0xffffffffu, s, 2);
            if (part == 0) sm.u.a.q[n] = s + p.q_b[n];
        }
        __syncthreads();
    } else {
        if (tid < KD) sm.u.a.q[tid] = p.q_b[tid];
        __syncthreads();
    }

    const int L = p.ulen[b];
    float e;
    {
        const float4* kp = reinterpret_cast<const float4*>(p.keys + ((size_t)tid * BATCH + b) * KD);
        const float4* qp = reinterpret_cast<const float4*>(sm.u.a.q);
        float s = 0.f;
#pragma unroll
        for (int i = 0; i < KD / 4; i++) {
            float4 kv = kp[i], qv = qp[i];
            s = fmaf(kv.x, qv.x, s); s = fmaf(kv.y, qv.y, s);
            s = fmaf(kv.z, qv.z, s); s = fmaf(kv.w, qv.w, s);
        }
        e = (tid < L) ? s : -10000.0f;
    }
    sm.u.a.red[tid] = e;
    __syncthreads();
    for (int s = 256; s > 0; s >>= 1) {
        if (tid < s) sm.u.a.red[tid] = fmaxf(sm.u.a.red[tid], sm.u.a.red[tid + s]);
        __syncthreads();
    }
    const float emax = sm.u.a.red[0];
    __syncthreads();

    float x = (tid < L) ? expf(e - emax) : 0.f;
    sm.u.a.red[tid] = x;
    __syncthreads();
    for (int s = 256; s > 0; s >>= 1) {
        if (tid < s) sm.u.a.red[tid] += sm.u.a.red[tid + s];
        __syncthreads();
    }
    const float inv = 1.f / sm.u.a.red[0];
    __syncthreads();

    float a = x * inv;
    sm.u.a.arr[tid] = a;
    attn_out[(size_t)b * TENC + tid] = a;
    __syncthreads();

    {
        int v = tid & 127, c4 = tid >> 7;
        float s = 0.f;
        int tb = c4 * 128;
#pragma unroll 8
        for (int tt = tb; tt < tb + 128; tt++)
            s = fmaf(sm.u.a.arr[tt], p.values[((size_t)tt * BATCH + b) * VD + v], s);
        sm.u.a.ps[c4][v] = s;
    }
    __syncthreads();
    if (tid < VD)
        g_ctx[b * VD + tid] = sm.u.a.ps[0][tid] + sm.u.a.ps[1][tid]
                            + sm.u.a.ps[2][tid] + sm.u.a.ps[3][tid];
}

// ---------------------------------------------------------------------------
// Combine p1 partials -> hid (leaky relu). 8192 float4s over 16 blocks.
// ---------------------------------------------------------------------------
__device__ void combine_hid_phase(const KP& p)
{
    int i = blockIdx.x * NTHR + threadIdx.x;
    if (i < BATCH * (D_DIM / 4)) {
        int m = i >> 7, kq = (i & 127) * 4;
        float4 v = ld4(p.p1_b + kq);
#pragma unroll
        for (int ss = 0; ss < 20; ss++) {
            float4 w = ldcg4(&g_Pp[((size_t)(ss * BATCH + m)) * D_DIM + kq]);
            v.x += w.x; v.y += w.y; v.z += w.z; v.w += w.w;
        }
        v.x = (v.x > 0.f) ? v.x : 0.01f * v.x;
        v.y = (v.y > 0.f) ? v.y : 0.01f * v.y;
        v.z = (v.z > 0.f) ? v.z : 0.01f * v.z;
        v.w = (v.w > 0.f) ? v.w : 0.01f * v.w;
        *reinterpret_cast<float4*>(&g_hid[m * D_DIM + kq]) = v;
    }
}

// ---------------------------------------------------------------------------
// Threefry-2x32 + logits combine + Gumbel argmax (blocks 0..63)
// ---------------------------------------------------------------------------
__device__ __forceinline__ void tf2x32(uint32_t k0, uint32_t k1, uint32_t x0, uint32_t x1,
                                       uint32_t& o0, uint32_t& o1)
{
    uint32_t ks2 = k0 ^ k1 ^ 0x1BD11BDAu;
    x0 += k0; x1 += k1;
#define TFR(r) { x0 += x1; x1 = (x1 << (r)) | (x1 >> (32 - (r))); x1 ^= x0; }
    TFR(13) TFR(15) TFR(26) TFR(6)   x0 += k1;  x1 += ks2 + 1u;
    TFR(17) TFR(29) TFR(16) TFR(24)  x0 += ks2; x1 += k0 + 2u;
    TFR(13) TFR(15) TFR(26) TFR(6)   x0 += k0;  x1 += k1 + 3u;
    TFR(17) TFR(29) TFR(16) TFR(24)  x0 += k1;  x1 += ks2 + 4u;
    TFR(13) TFR(15) TFR(26) TFR(6)   x0 += ks2; x1 += k0 + 5u;
#undef TFR
    o0 = x0; o1 = x1;
}

__device__ void sample_phase(const KP& p, Smem& sm, int step)
{
    if (blockIdx.x >= BATCH) return;
    const int b = blockIdx.x, tid = threadIdx.x;
    uint32_t fk0, fk1;
    tf2x32(0u, 1u, 0u, (uint32_t)step, fk0, fk1);

    float* outl = p.out_logits + ((size_t)step * BATCH + b) * VOCAB;
    float best = -__int_as_float(0x7f800000);
    int bidx = 0;
    for (int v = tid; v < VOCAB; v += NTHR) {
        float lg = p.p2_b[v];
#pragma unroll
        for (int ss = 0; ss < LKS; ss++)
            lg += __ldcg(&g_Lp[((size_t)(ss * BATCH + b)) * LPLD + v]);
        outl[v] = lg;
        uint32_t o0, o1;
        tf2x32(fk0, fk1, 0u, (uint32_t)(b * VOCAB + v), o0, o1);
        uint32_t bits = o0 ^ o1;
        float u = __uint_as_float((bits >> 9) | 0x3f800000u) - 1.0f;
        float gmb = -logf(1e-10f - logf(u + 1e-10f));
        float val = lg + gmb;
        if (val > best) { best = val; bidx = v; }
    }
    sm.u.s.sv[tid] = best; sm.u.s.si[tid] = bidx;
    __syncthreads();
    for (int s = 256; s > 0; s >>= 1) {
        if (tid < s) {
            if (sm.u.s.sv[tid + s] > sm.u.s.sv[tid] ||
                (sm.u.s.sv[tid + s] == sm.u.s.sv[tid] && sm.u.s.si[tid + s] < sm.u.s.si[tid])) {
                sm.u.s.sv[tid] = sm.u.s.sv[tid + s]; sm.u.s.si[tid] = sm.u.s.si[tid + s];
            }
        }
        __syncthreads();
    }
    if (tid == 0) p.out_gen[step * BATCH + b] = (float)sm.u.s.si[0];
    __syncthreads();
}

// ---------------------------------------------------------------------------
// The megakernel — 7 barriers/step
// ---------------------------------------------------------------------------
__global__ __launch_bounds__(NTHR, 2) void mega_kernel(KP p)
{
    __shared__ Smem sm;
    const int tid = threadIdx.x;

    for (int i = blockIdx.x * NTHR + tid; i < BATCH * D_DIM; i += gridDim.x * NTHR) {
        g_h1[i] = 0.f; g_c1[i] = 0.f;
        g_h2[i] = 0.f; g_c2[i] = 0.f;
        g_h3[i] = 0.f; g_c3[i] = 0.f;
        if (i < BATCH * VD) g_ctx[i] = 0.f;
    }
    grid_sync();

    attn_phase(p, sm, false, g_attn_scratch);
    grid_sync();

    for (int t = 0; t < TDEC; t++) {
        if (t > 0) sample_phase(p, sm, t - 1);
        gemm_phase<0, 16, 12, 96, 3, true,  true>(p, sm, t, g_Gp);   // lstm0 + cell
        grid_sync();
        gemm_phase<1, 16, 16, 64, 2, false, true>(p, sm, t, g_Gp);   // lstm1 + cell
        grid_sync();
        gemm_phase<2, 16, 16, 64, 2, false, true>(p, sm, t, g_Gp);   // lstm2 + cell
        grid_sync();
        attn_phase(p, sm, true, p.out_attn + (size_t)t * BATCH * TENC);
        grid_sync();
        gemm_phase<3, 4, 20, 32, 1, false, false>(p, sm, t, g_Pp);   // p1
        grid_sync();
        combine_hid_phase(p);
        grid_sync();
        logits_mma_phase<79>(p, sm, g_Lp);                            // logits tf32x3
        grid_sync();
    }
    sample_phase(p, sm, TDEC - 1);
}

// ---------------------------------------------------------------------------
// Host launcher — single graph node
// ---------------------------------------------------------------------------
extern "C" void kernel_launch(void* const* d_in, const int* in_sizes, int n_in,
                              void* d_out, int out_size)
{
    (void)in_sizes; (void)n_in;
    KP p;
    p.inputs = (const int*)  d_in[0];
    p.keys   = (const float*)d_in[2];
    p.values = (const float*)d_in[3];
    p.ulen   = (const int*)  d_in[4];
    p.emb    = (const float*)d_in[5];
    p.w_ih0 = (const float*)d_in[6];  p.w_hh0 = (const float*)d_in[7];
    p.b_ih0 = (const float*)d_in[8];  p.b_hh0 = (const float*)d_in[9];
    p.w_ih1 = (const float*)d_in[10]; p.w_hh1 = (const float*)d_in[11];
    p.b_ih1 = (const float*)d_in[12]; p.b_hh1 = (const float*)d_in[13];
    p.w_ih2 = (const float*)d_in[14]; p.w_hh2 = (const float*)d_in[15];
    p.b_ih2 = (const float*)d_in[16]; p.b_hh2 = (const float*)d_in[17];
    p.q_w  = (const float*)d_in[18];  p.q_b  = (const float*)d_in[19];
    p.p1_w = (const float*)d_in[20];  p.p1_b = (const float*)d_in[21];
    p.p2_b = (const float*)d_in[22];

    float* out = (float*)d_out;
    const size_t L_LOG = (size_t)TDEC * BATCH * VOCAB;
    const size_t L_ATT = (size_t)TDEC * BATCH * TENC;
    const size_t TOTAL = L_LOG + L_ATT + (size_t)TDEC * BATCH;
    const bool full = (size_t)out_size >= TOTAL;

    void* vp;
    cudaGetSymbolAddress(&vp, g_attn_scratch);
    float* pAS = (float*)vp;
    cudaGetSymbolAddress(&vp, g_gen_scratch);
    float* pGS = (float*)vp;

    p.out_logits = out;
    p.out_attn   = full ? out + L_LOG         : pAS;
    p.out_gen    = full ? out + L_LOG + L_ATT : pGS;

    int dev = 0, sms = 0;
    cudaGetDevice(&dev);
    cudaDeviceGetAttribute(&sms, cudaDevAttrMultiProcessorCount, dev);
    if (sms < 64) sms = 64;

    int occ = 1;
    cudaOccupancyMaxActiveBlocksPerMultiprocessor(&occ, mega_kernel, NTHR, 0);
    if (occ < 1) occ = 1;
    if (occ > 2) occ = 2;

    mega_kernel<<<sms * occ, NTHR>>>(p);
}

// round 10
// speedup vs baseline: 1.4228x; 1.4228x over previous
#include <cuda_runtime.h>
#include <math.h>
#include <stdint.h>
#include <stddef.h>

#define D_DIM   512
#define KD      128
#define VD      128
#define VOCAB   10001
#define BATCH   64
#define TDEC    192
#define TENC    512
#define NTHR    512
#define LPLD    10016          // padded row stride for logits partials

// ---------------------------------------------------------------------------
// Persistent state / scratch (device globals; no allocation allowed)
// ---------------------------------------------------------------------------
__device__ __align__(16) float g_h1[BATCH * D_DIM], g_c1[BATCH * D_DIM];
__device__ __align__(16) float g_h2[BATCH * D_DIM], g_c2[BATCH * D_DIM];
__device__ __align__(16) float g_h3[BATCH * D_DIM], g_c3[BATCH * D_DIM];
__device__ __align__(16) float g_ctx[BATCH * VD];
__device__ __align__(16) float g_hid[BATCH * D_DIM];
__device__ __align__(16) float g_Gp[16 * BATCH * 2048];   // LSTM gate partials (interleaved n)
__device__ __align__(16) float g_Pp[20 * BATCH * D_DIM];  // p1 partials
__device__ __align__(16) float g_Lp[8 * BATCH * LPLD];    // logits partials
__device__ __align__(16) float g_attn_scratch[BATCH * TENC];
__device__ __align__(16) float g_gen_scratch [TDEC * BATCH];
__device__ unsigned g_cnt[32];             // per-n-tile split counters (lstm 0-15, p1 16-19)
__device__ unsigned g_grp[16 * 32];        // barrier group counters (128B apart)
__device__ unsigned g_root;                // barrier root counter
__device__ unsigned g_rel;                 // barrier release generation

struct KP {
    const int*   inputs;
    const float* keys;   const float* values; const int* ulen;
    const float* emb;
    const float* w_ih0; const float* w_hh0; const float* b_ih0; const float* b_hh0;
    const float* w_ih1; const float* w_hh1; const float* b_ih1; const float* b_hh1;
    const float* w_ih2; const float* w_hh2; const float* b_ih2; const float* b_hh2;
    const float* q_w;  const float* q_b;
    const float* p1_w; const float* p1_b; const float* p2_b;
    float* out_logits; float* out_attn; float* out_gen;
};

struct __align__(16) Smem {
    union {
        struct { float As[32][64]; float Bs[32][128]; } g;    // 8KB + 16KB
        struct { float h3s[D_DIM]; float q[KD]; float arr[TENC];
                 float red[NTHR]; float ps[4][VD]; } a;
        struct { float sv[NTHR]; int si[NTHR]; } s;
    } u;
    int flag;
};

// ---------------------------------------------------------------------------
// Hierarchical grid barrier: 16 groups -> root -> release generation.
// Arrival atomics parallelized 16-way (separate 128B lines).
// ---------------------------------------------------------------------------
__device__ __forceinline__ void grid_sync()
{
    __syncthreads();
    if (threadIdx.x == 0) {
        __threadfence();
        const unsigned gen = *(volatile unsigned*)&g_rel;
        const int grp = blockIdx.x & 15;
        const unsigned gsz = (gridDim.x >> 4) + (((gridDim.x & 15) > (unsigned)grp) ? 1u : 0u);
        if (atomicAdd(&g_grp[grp * 32], 1u) == gsz - 1u) {
            atomicExch(&g_grp[grp * 32], 0u);
            if (atomicAdd(&g_root, 1u) == 15u) {
                atomicExch(&g_root, 0u);
                __threadfence();
                atomicExch(&g_rel, gen + 1u);
            }
        }
        while (*(volatile unsigned*)&g_rel == gen) { }
        __threadfence();
    }
    __syncthreads();
}

// ---------------------------------------------------------------------------
// Virtual-operand loaders.  Mutable state via __ldcg (L2-coherent).
// ---------------------------------------------------------------------------
__device__ __forceinline__ float4 ld4(const float* p) { return *reinterpret_cast<const float4*>(p); }
__device__ __forceinline__ float4 ldcg4(const float* p) { return __ldcg(reinterpret_cast<const float4*>(p)); }

template<int MODE>
__device__ __forceinline__ float4 loadA(const KP& p, int tok, int m, int k)
{
    if (MODE == 0) {
        if (k < 512)      return ld4(p.emb + (size_t)tok * D_DIM + k);
        else if (k < 640) return ldcg4(g_ctx + m * VD + (k - 512));
        else              return ldcg4(g_h1 + m * D_DIM + (k - 640));
    } else if (MODE == 1) {
        return (k < 512) ? ldcg4(g_h1 + m * D_DIM + k) : ldcg4(g_h2 + m * D_DIM + (k - 512));
    } else if (MODE == 2) {
        return (k < 512) ? ldcg4(g_h2 + m * D_DIM + k) : ldcg4(g_h3 + m * D_DIM + (k - 512));
    } else if (MODE == 3) {
        return (k < 512) ? ldcg4(g_h3 + m * D_DIM + k) : ldcg4(g_ctx + m * VD + (k - 512));
    } else {
        return ldcg4(g_hid + m * D_DIM + k);
    }
}

// LSTM modes use gate-interleaved virtual columns: n -> phys row (n&3)*512 + (n>>2)
template<int MODE>
__device__ __forceinline__ float4 loadB(const KP& p, int n, int k)
{
    if (MODE <= 2) {
        int row = (n & 3) * 512 + (n >> 2);
        if (MODE == 0) return (k < 640) ? ld4(p.w_ih0 + (size_t)row * 640 + k)
                                        : ld4(p.w_hh0 + (size_t)row * 512 + (k - 640));
        if (MODE == 1) return (k < 512) ? ld4(p.w_ih1 + (size_t)row * 512 + k)
                                        : ld4(p.w_hh1 + (size_t)row * 512 + (k - 512));
        return (k < 512) ? ld4(p.w_ih2 + (size_t)row * 512 + k)
                         : ld4(p.w_hh2 + (size_t)row * 512 + (k - 512));
    }
    if (MODE == 3) return ld4(p.p1_w + (size_t)n * 640 + k);
    if (n < VOCAB) return ld4(p.emb + (size_t)n * D_DIM + k);
    return make_float4(0.f, 0.f, 0.f, 0.f);
}

// ---------------------------------------------------------------------------
// LSTM cell combine (last-arriving split block; deterministic ss order)
// Tile nt covers units u0..u0+31 (all gates). 2048 (m,u) pairs / 512 thr = 4.
// ---------------------------------------------------------------------------
template<int MODE, int KSPLIT>
__device__ void lstm_combine(const KP& p, int nt)
{
    const int tid = threadIdx.x;
    const float* bih = (MODE == 0) ? p.b_ih0 : (MODE == 1) ? p.b_ih1 : p.b_ih2;
    const float* bhh = (MODE == 0) ? p.b_hh0 : (MODE == 1) ? p.b_hh1 : p.b_hh2;
    float* c = (MODE == 0) ? g_c1 : (MODE == 1) ? g_c2 : g_c3;
    float* h = (MODE == 0) ? g_h1 : (MODE == 1) ? g_h2 : g_h3;
    const int u0 = nt * 32;
#pragma unroll
    for (int j = 0; j < 4; j++) {
        int pair = tid + j * NTHR;
        int m = pair >> 5, u = u0 + (pair & 31);
        float4 s = make_float4(0.f, 0.f, 0.f, 0.f);
#pragma unroll
        for (int ss = 0; ss < KSPLIT; ss++) {
            float4 v = ldcg4(&g_Gp[((size_t)(ss * BATCH + m)) * 2048 + u * 4]);
            s.x += v.x; s.y += v.y; s.z += v.z; s.w += v.w;
        }
        float gi = s.x + bih[u]        + bhh[u];
        float gf = s.y + bih[512 + u]  + bhh[512 + u];
        float gg = s.z + bih[1024 + u] + bhh[1024 + u];
        float go = s.w + bih[1536 + u] + bhh[1536 + u];
        float si = 1.f / (1.f + expf(-gi));
        float sf = 1.f / (1.f + expf(-gf));
        float so = 1.f / (1.f + expf(-go));
        float cc = sf * __ldcg(&c[m * D_DIM + u]) + si * tanhf(gg);
        c[m * D_DIM + u] = cc;
        h[m * D_DIM + u] = so * tanhf(cc);
    }
}

// hid combine (p1): tile nt covers hid cols n0..n0+127. 2048 float4 / 512 = 4.
template<int KSPLIT>
__device__ void hid_combine(const KP& p, int nt)
{
    const int tid = threadIdx.x;
    const int n0 = nt * 128;
#pragma unroll
    for (int j = 0; j < 4; j++) {
        int item = tid + j * NTHR;
        int m = item >> 5, nq = n0 + (item & 31) * 4;
        float4 v = ld4(p.p1_b + nq);
#pragma unroll
        for (int ss = 0; ss < KSPLIT; ss++) {
            float4 w = ldcg4(&g_Pp[((size_t)(ss * BATCH + m)) * D_DIM + nq]);
            v.x += w.x; v.y += w.y; v.z += w.z; v.w += w.w;
        }
        v.x = (v.x > 0.f) ? v.x : 0.01f * v.x;
        v.y = (v.y > 0.f) ? v.y : 0.01f * v.y;
        v.z = (v.z > 0.f) ? v.z : 0.01f * v.z;
        v.w = (v.w > 0.f) ? v.w : 0.01f * v.w;
        *reinterpret_cast<float4*>(&g_hid[m * D_DIM + nq]) = v;
    }
}

// ---------------------------------------------------------------------------
// GEMM: 64x128 tile, 512 threads, 4x4 thread-tile, 32-deep chunks, prefetch.
// FUSE: 0 none, 1 lstm cell, 2 hid combine.  CNTOFF: counter array offset.
// ---------------------------------------------------------------------------
template<int MODE, int NT, int KSPLIT, int KC, int NCH, bool EXCL, int FUSE, int CNTOFF>
__device__ void gemm_phase(const KP& p, Smem& sm, int step, float* out)
{
    constexpr int NTILES = NT * KSPLIT;
    const int tid = threadIdx.x;
    const int ty = tid >> 5, tx = tid & 31;      // 16 x 32 compute grid
    const int arow = tid & 63;
    const int akg  = (tid >> 6) * 4;             // 0..28
    const int brow = tid & 127;
    const int bkg  = (tid >> 7) * 4;             // 0,4,8,12

    int bid = blockIdx.x, stride = gridDim.x;
    if (EXCL) { if (bid < 64) return; bid -= 64; stride -= 64; }

    int tok = 0;
    if (MODE == 0) tok = p.inputs[step * BATCH + arow];

    for (int tile = bid; tile < NTILES; tile += stride) {
        const int nt = tile % NT, ks = tile / NT;
        const int n0 = nt * 128, kb = ks * KC;
        float acc[4][4] = {};

        float4 rA  = loadA<MODE>(p, tok, arow, kb + akg);
        float4 rB0 = loadB<MODE>(p, n0 + brow, kb + bkg);
        float4 rB1 = loadB<MODE>(p, n0 + brow, kb + bkg + 16);

#pragma unroll 1
        for (int ch = 0; ch < NCH; ch++) {
            __syncthreads();
            sm.u.g.As[akg + 0][arow] = rA.x;  sm.u.g.As[akg + 1][arow] = rA.y;
            sm.u.g.As[akg + 2][arow] = rA.z;  sm.u.g.As[akg + 3][arow] = rA.w;
            sm.u.g.Bs[bkg + 0][brow] = rB0.x; sm.u.g.Bs[bkg + 1][brow] = rB0.y;
            sm.u.g.Bs[bkg + 2][brow] = rB0.z; sm.u.g.Bs[bkg + 3][brow] = rB0.w;
            sm.u.g.Bs[bkg + 16][brow] = rB1.x; sm.u.g.Bs[bkg + 17][brow] = rB1.y;
            sm.u.g.Bs[bkg + 18][brow] = rB1.z; sm.u.g.Bs[bkg + 19][brow] = rB1.w;
            __syncthreads();
            if (ch + 1 < NCH) {
                int k2 = kb + (ch + 1) * 32;
                rA  = loadA<MODE>(p, tok, arow, k2 + akg);
                rB0 = loadB<MODE>(p, n0 + brow, k2 + bkg);
                rB1 = loadB<MODE>(p, n0 + brow, k2 + bkg + 16);
            }
#pragma unroll 8
            for (int kk = 0; kk < 32; kk++) {
                float4 a4 = *reinterpret_cast<const float4*>(&sm.u.g.As[kk][ty * 4]);
                float4 b4 = *reinterpret_cast<const float4*>(&sm.u.g.Bs[kk][tx * 4]);
                acc[0][0] = fmaf(a4.x, b4.x, acc[0][0]);
                acc[0][1] = fmaf(a4.x, b4.y, acc[0][1]);
                acc[0][2] = fmaf(a4.x, b4.z, acc[0][2]);
                acc[0][3] = fmaf(a4.x, b4.w, acc[0][3]);
                acc[1][0] = fmaf(a4.y, b4.x, acc[1][0]);
                acc[1][1] = fmaf(a4.y, b4.y, acc[1][1]);
                acc[1][2] = fmaf(a4.y, b4.z, acc[1][2]);
                acc[1][3] = fmaf(a4.y, b4.w, acc[1][3]);
                acc[2][0] = fmaf(a4.z, b4.x, acc[2][0]);
                acc[2][1] = fmaf(a4.z, b4.y, acc[2][1]);
                acc[2][2] = fmaf(a4.z, b4.z, acc[2][2]);
                acc[2][3] = fmaf(a4.z, b4.w, acc[2][3]);
                acc[3][0] = fmaf(a4.w, b4.x, acc[3][0]);
                acc[3][1] = fmaf(a4.w, b4.y, acc[3][1]);
                acc[3][2] = fmaf(a4.w, b4.z, acc[3][2]);
                acc[3][3] = fmaf(a4.w, b4.w, acc[3][3]);
            }
        }

        // ---- epilogue: store partials ----
        if (MODE == 4) {
            const bool edge = (n0 + 127 >= VOCAB);
#pragma unroll
            for (int i = 0; i < 4; i++) {
                size_t row = ((size_t)(ks * BATCH + ty * 4 + i)) * LPLD;
                int n = n0 + tx * 4;
                if (!edge) {
                    *reinterpret_cast<float4*>(&out[row + n]) =
                        make_float4(acc[i][0], acc[i][1], acc[i][2], acc[i][3]);
                } else {
#pragma unroll
                    for (int j = 0; j < 4; j++)
                        if (n + j < VOCAB) out[row + n + j] = acc[i][j];
                }
            }
        } else {
            const int NNout = (MODE == 3) ? 512 : 2048;
#pragma unroll
            for (int i = 0; i < 4; i++)
                *reinterpret_cast<float4*>(
                    &out[((size_t)(ks * BATCH + ty * 4 + i)) * NNout + n0 + tx * 4]) =
                    make_float4(acc[i][0], acc[i][1], acc[i][2], acc[i][3]);
        }

        if (FUSE != 0) {
            __syncthreads();
            if (tid == 0) {
                __threadfence();
                sm.flag = (atomicAdd(&g_cnt[CNTOFF + nt], 1u) == KSPLIT - 1);
            }
            __syncthreads();
            if (sm.flag) {
                __threadfence();
                if (FUSE == 1) lstm_combine<MODE, KSPLIT>(p, nt);
                else           hid_combine<KSPLIT>(p, nt);
                if (tid == 0) g_cnt[CNTOFF + nt] = 0;
            }
        }
    }
}

// ---------------------------------------------------------------------------
// Query + attention + context.  One block per batch element (blocks 0..63).
// ---------------------------------------------------------------------------
__device__ void attn_phase(const KP& p, Smem& sm, bool with_q, float* attn_out)
{
    if (blockIdx.x >= BATCH) return;
    const int b = blockIdx.x, tid = threadIdx.x;

    if (with_q) {
        sm.u.a.h3s[tid] = __ldcg(&g_h3[b * D_DIM + tid]);
        __syncthreads();
        {
            int n = tid >> 2, part = tid & 3;
            const float4* wp = reinterpret_cast<const float4*>(p.q_w + (size_t)n * D_DIM + part * 128);
            const float4* hp = reinterpret_cast<const float4*>(sm.u.a.h3s + part * 128);
            float s = 0.f;
#pragma unroll
            for (int i = 0; i < 32; i++) {
                float4 wv = wp[i], hv = hp[i];
                s = fmaf(wv.x, hv.x, s); s = fmaf(wv.y, hv.y, s);
                s = fmaf(wv.z, hv.z, s); s = fmaf(wv.w, hv.w, s);
            }
            s += __shfl_down_sync(0xffffffffu, s, 1);
            s += __shfl_down_sync(0xffffffffu, s, 2);
            if (part == 0) sm.u.a.q[n] = s + p.q_b[n];
        }
        __syncthreads();
    } else {
        if (tid < KD) sm.u.a.q[tid] = p.q_b[tid];
        __syncthreads();
    }

    const int L = p.ulen[b];
    float e;
    {
        const float4* kp = reinterpret_cast<const float4*>(p.keys + ((size_t)tid * BATCH + b) * KD);
        const float4* qp = reinterpret_cast<const float4*>(sm.u.a.q);
        float s = 0.f;
#pragma unroll
        for (int i = 0; i < KD / 4; i++) {
            float4 kv = kp[i], qv = qp[i];
            s = fmaf(kv.x, qv.x, s); s = fmaf(kv.y, qv.y, s);
            s = fmaf(kv.z, qv.z, s); s = fmaf(kv.w, qv.w, s);
        }
        e = (tid < L) ? s : -10000.0f;
    }
    sm.u.a.red[tid] = e;
    __syncthreads();
    for (int s = 256; s > 0; s >>= 1) {
        if (tid < s) sm.u.a.red[tid] = fmaxf(sm.u.a.red[tid], sm.u.a.red[tid + s]);
        __syncthreads();
    }
    const float emax = sm.u.a.red[0];
    __syncthreads();

    float x = (tid < L) ? expf(e - emax) : 0.f;
    sm.u.a.red[tid] = x;
    __syncthreads();
    for (int s = 256; s > 0; s >>= 1) {
        if (tid < s) sm.u.a.red[tid] += sm.u.a.red[tid + s];
        __syncthreads();
    }
    const float inv = 1.f / sm.u.a.red[0];
    __syncthreads();

    float a = x * inv;
    sm.u.a.arr[tid] = a;
    attn_out[(size_t)b * TENC + tid] = a;
    __syncthreads();

    {
        int v = tid & 127, c4 = tid >> 7;
        float s = 0.f;
        int tb = c4 * 128;
#pragma unroll 8
        for (int tt = tb; tt < tb + 128; tt++)
            s = fmaf(sm.u.a.arr[tt], p.values[((size_t)tt * BATCH + b) * VD + v], s);
        sm.u.a.ps[c4][v] = s;
    }
    __syncthreads();
    if (tid < VD)
        g_ctx[b * VD + tid] = sm.u.a.ps[0][tid] + sm.u.a.ps[1][tid]
                            + sm.u.a.ps[2][tid] + sm.u.a.ps[3][tid];
}

// ---------------------------------------------------------------------------
// Threefry-2x32 + logits combine + Gumbel argmax (blocks 0..63)
// ---------------------------------------------------------------------------
__device__ __forceinline__ void tf2x32(uint32_t k0, uint32_t k1, uint32_t x0, uint32_t x1,
                                       uint32_t& o0, uint32_t& o1)
{
    uint32_t ks2 = k0 ^ k1 ^ 0x1BD11BDAu;
    x0 += k0; x1 += k1;
#define TFR(r) { x0 += x1; x1 = (x1 << (r)) | (x1 >> (32 - (r))); x1 ^= x0; }
    TFR(13) TFR(15) TFR(26) TFR(6)   x0 += k1;  x1 += ks2 + 1u;
    TFR(17) TFR(29) TFR(16) TFR(24)  x0 += ks2; x1 += k0 + 2u;
    TFR(13) TFR(15) TFR(26) TFR(6)   x0 += k0;  x1 += k1 + 3u;
    TFR(17) TFR(29) TFR(16) TFR(24)  x0 += k1;  x1 += ks2 + 4u;
    TFR(13) TFR(15) TFR(26) TFR(6)   x0 += ks2; x1 += k0 + 5u;
#undef TFR
    o0 = x0; o1 = x1;
}

__device__ void sample_phase(const KP& p, Smem& sm, int step)
{
    if (blockIdx.x >= BATCH) return;
    const int b = blockIdx.x, tid = threadIdx.x;
    uint32_t fk0, fk1;
    tf2x32(0u, 1u, 0u, (uint32_t)step, fk0, fk1);

    float* outl = p.out_logits + ((size_t)step * BATCH + b) * VOCAB;
    float best = -__int_as_float(0x7f800000);
    int bidx = 0;
    for (int v = tid; v < VOCAB; v += NTHR) {
        float lg = p.p2_b[v];
#pragma unroll
        for (int ss = 0; ss < 8; ss++)
            lg += __ldcg(&g_Lp[((size_t)(ss * BATCH + b)) * LPLD + v]);
        outl[v] = lg;
        uint32_t o0, o1;
        tf2x32(fk0, fk1, 0u, (uint32_t)(b * VOCAB + v), o0, o1);
        uint32_t bits = o0 ^ o1;
        float u = __uint_as_float((bits >> 9) | 0x3f800000u) - 1.0f;
        float gmb = -logf(1e-10f - logf(u + 1e-10f));
        float val = lg + gmb;
        if (val > best) { best = val; bidx = v; }
    }
    sm.u.s.sv[tid] = best; sm.u.s.si[tid] = bidx;
    __syncthreads();
    for (int s = 256; s > 0; s >>= 1) {
        if (tid < s) {
            if (sm.u.s.sv[tid + s] > sm.u.s.sv[tid] ||
                (sm.u.s.sv[tid + s] == sm.u.s.sv[tid] && sm.u.s.si[tid + s] < sm.u.s.si[tid])) {
                sm.u.s.sv[tid] = sm.u.s.sv[tid + s]; sm.u.s.si[tid] = sm.u.s.si[tid + s];
            }
        }
        __syncthreads();
    }
    if (tid == 0) p.out_gen[step * BATCH + b] = (float)sm.u.s.si[0];
    __syncthreads();
}

// ---------------------------------------------------------------------------
// The megakernel — 6 barriers/step
// ---------------------------------------------------------------------------
__global__ __launch_bounds__(NTHR, 2) void mega_kernel(KP p)
{
    __shared__ Smem sm;
    const int tid = threadIdx.x;

    for (int i = blockIdx.x * NTHR + tid; i < BATCH * D_DIM; i += gridDim.x * NTHR) {
        g_h1[i] = 0.f; g_c1[i] = 0.f;
        g_h2[i] = 0.f; g_c2[i] = 0.f;
        g_h3[i] = 0.f; g_c3[i] = 0.f;
        if (i < BATCH * VD) g_ctx[i] = 0.f;
    }
    grid_sync();

    attn_phase(p, sm, false, g_attn_scratch);
    grid_sync();

    for (int t = 0; t < TDEC; t++) {
        if (t > 0) sample_phase(p, sm, t - 1);
        gemm_phase<0, 16, 12, 96, 3, true,  1, 0 >(p, sm, t, g_Gp);  // lstm0 + cell
        grid_sync();
        gemm_phase<1, 16, 16, 64, 2, false, 1, 0 >(p, sm, t, g_Gp);  // lstm1 + cell
        grid_sync();
        gemm_phase<2, 16, 16, 64, 2, false, 1, 0 >(p, sm, t, g_Gp);  // lstm2 + cell
        grid_sync();
        attn_phase(p, sm, true, p.out_attn + (size_t)t * BATCH * TENC);
        grid_sync();
        gemm_phase<3, 4, 20, 32, 1, false, 2, 16>(p, sm, t, g_Pp);   // p1 + hid
        grid_sync();
        gemm_phase<4, 79, 8, 64, 2, false, 0, 0 >(p, sm, t, g_Lp);   // logits
        grid_sync();
    }
    sample_phase(p, sm, TDEC - 1);
}

// ---------------------------------------------------------------------------
// Host launcher — single graph node
// ---------------------------------------------------------------------------
extern "C" void kernel_launch(void* const* d_in, const int* in_sizes, int n_in,
                              void* d_out, int out_size)
{
    (void)in_sizes; (void)n_in;
    KP p;
    p.inputs = (const int*)  d_in[0];
    p.keys   = (const float*)d_in[2];
    p.values = (const float*)d_in[3];
    p.ulen   = (const int*)  d_in[4];
    p.emb    = (const float*)d_in[5];
    p.w_ih0 = (const float*)d_in[6];  p.w_hh0 = (const float*)d_in[7];
    p.b_ih0 = (const float*)d_in[8];  p.b_hh0 = (const float*)d_in[9];
    p.w_ih1 = (const float*)d_in[10]; p.w_hh1 = (const float*)d_in[11];
    p.b_ih1 = (const float*)d_in[12]; p.b_hh1 = (const float*)d_in[13];
    p.w_ih2 = (const float*)d_in[14]; p.w_hh2 = (const float*)d_in[15];
    p.b_ih2 = (const float*)d_in[16]; p.b_hh2 = (const float*)d_in[17];
    p.q_w  = (const float*)d_in[18];  p.q_b  = (const float*)d_in[19];
    p.p1_w = (const float*)d_in[20];  p.p1_b = (const float*)d_in[21];
    p.p2_b = (const float*)d_in[22];

    float* out = (float*)d_out;
    const size_t L_LOG = (size_t)TDEC * BATCH * VOCAB;
    const size_t L_ATT = (size_t)TDEC * BATCH * TENC;
    const size_t TOTAL = L_LOG + L_ATT + (size_t)TDEC * BATCH;
    const bool full = (size_t)out_size >= TOTAL;

    void* vp;
    cudaGetSymbolAddress(&vp, g_attn_scratch);
    float* pAS = (float*)vp;
    cudaGetSymbolAddress(&vp, g_gen_scratch);
    float* pGS = (float*)vp;

    p.out_logits = out;
    p.out_attn   = full ? out + L_LOG         : pAS;
    p.out_gen    = full ? out + L_LOG + L_ATT : pGS;

    int dev = 0, sms = 0;
    cudaGetDevice(&dev);
    cudaDeviceGetAttribute(&sms, cudaDevAttrMultiProcessorCount, dev);
    if (sms < 64) sms = 64;

    int occ = 1;
    cudaOccupancyMaxActiveBlocksPerMultiprocessor(&occ, mega_kernel, NTHR, 0);
    if (occ < 1) occ = 1;
    if (occ > 2) occ = 2;

    mega_kernel<<<sms * occ, NTHR>>>(p);
}

// round 11
// speedup vs baseline: 1.7143x; 1.2049x over previous
#include <cuda_runtime.h>
#include <math.h>
#include <stdint.h>
#include <stddef.h>

#define D_DIM   512
#define KD      128
#define VD      128
#define VOCAB   10001
#define BATCH   64
#define TDEC    192
#define TENC    512
#define NTHR    512
#define LPLD    10016          // padded row stride for logits partials
#define LKS     4              // logits K-split

// ---------------------------------------------------------------------------
// Persistent state / scratch (device globals; no allocation allowed)
// ---------------------------------------------------------------------------
__device__ __align__(16) float g_h1[BATCH * D_DIM], g_c1[BATCH * D_DIM];
__device__ __align__(16) float g_h2[BATCH * D_DIM], g_c2[BATCH * D_DIM];
__device__ __align__(16) float g_h3[BATCH * D_DIM], g_c3[BATCH * D_DIM];
__device__ __align__(16) float g_ctx[BATCH * VD];
__device__ __align__(16) float g_hid[BATCH * D_DIM];
__device__ __align__(16) float g_h3s[2][BATCH * D_DIM];   // snapshots for branch
__device__ __align__(16) float g_ctxs[2][BATCH * VD];
__device__ __align__(16) float g_Gp[9 * BATCH * 2048];    // LSTM gate partials
__device__ __align__(16) float g_Pp[20 * BATCH * D_DIM];  // p1 partials
__device__ __align__(16) float g_Lp[LKS * BATCH * LPLD];  // logits partials
__device__ __align__(16) float g_attn_scratch[BATCH * TENC];
__device__ __align__(16) float g_gen_scratch [TDEC * BATCH];
__device__ unsigned g_cnt[32];             // per-n-tile split counters
__device__ unsigned g_bar_count, g_bar_gen;                // full-grid barrier
__device__ __align__(128) unsigned g_sbar[32];             // spine barrier [0]=cnt [16]=gen
__device__ __align__(128) unsigned g_bbar[32];             // branch barrier
__device__ __align__(128) unsigned g_sready;               // steps published by spine
__device__ __align__(128) unsigned g_bdone;                // steps finished by branch

struct KP {
    const int*   inputs;
    const float* keys;   const float* values; const int* ulen;
    const float* emb;
    const float* w_ih0; const float* w_hh0; const float* b_ih0; const float* b_hh0;
    const float* w_ih1; const float* w_hh1; const float* b_ih1; const float* b_hh1;
    const float* w_ih2; const float* w_hh2; const float* b_ih2; const float* b_hh2;
    const float* q_w;  const float* q_b;
    const float* p1_w; const float* p1_b; const float* p2_b;
    float* out_logits; float* out_attn; float* out_gen;
    int nsp;           // spine block count; branch = grid - nsp
};

struct __align__(16) Smem {
    union {
        struct { float As[32][64]; float Bs[32][128]; } g;    // 8KB + 16KB
        struct { float h3s[D_DIM]; float q[KD]; float arr[TENC];
                 float red[NTHR]; float ps[4][VD]; } a;
        struct { float sv[NTHR]; int si[NTHR]; } s;
    } u;
    int flag;
};

// ---------------------------------------------------------------------------
// Barriers
// ---------------------------------------------------------------------------
__device__ __forceinline__ void full_sync()
{
    __syncthreads();
    if (threadIdx.x == 0) {
        __threadfence();
        unsigned my = *((volatile unsigned*)&g_bar_gen);
        if (atomicAdd(&g_bar_count, 1u) == gridDim.x - 1) {
            atomicExch(&g_bar_count, 0u);
            __threadfence();
            atomicAdd(&g_bar_gen, 1u);
        } else {
            while (*((volatile unsigned*)&g_bar_gen) == my) { }
        }
        __threadfence();
    }
    __syncthreads();
}

__device__ __forceinline__ void part_sync(unsigned* cnt, unsigned* gen, unsigned n)
{
    __syncthreads();
    if (threadIdx.x == 0) {
        __threadfence();
        unsigned my = *((volatile unsigned*)gen);
        if (atomicAdd(cnt, 1u) == n - 1) {
            atomicExch(cnt, 0u);
            __threadfence();
            atomicAdd(gen, 1u);
        } else {
            while (*((volatile unsigned*)gen) == my) { }
        }
        __threadfence();
    }
    __syncthreads();
}

// ---------------------------------------------------------------------------
// Virtual-operand loaders.  Mutable state via __ldcg (L2-coherent).
// ---------------------------------------------------------------------------
__device__ __forceinline__ float4 ld4(const float* p) { return *reinterpret_cast<const float4*>(p); }
__device__ __forceinline__ float4 ldcg4(const float* p) { return __ldcg(reinterpret_cast<const float4*>(p)); }

template<int MODE>
__device__ __forceinline__ float4 loadA(const KP& p, int tok, int m, int k, int buf)
{
    if (MODE == 0) {
        if (k < 512)      return ld4(p.emb + (size_t)tok * D_DIM + k);
        else if (k < 640) return ldcg4(g_ctx + m * VD + (k - 512));
        else              return ldcg4(g_h1 + m * D_DIM + (k - 640));
    } else if (MODE == 1) {
        return (k < 512) ? ldcg4(g_h1 + m * D_DIM + k) : ldcg4(g_h2 + m * D_DIM + (k - 512));
    } else if (MODE == 2) {
        return (k < 512) ? ldcg4(g_h2 + m * D_DIM + k) : ldcg4(g_h3 + m * D_DIM + (k - 512));
    } else if (MODE == 3) {
        return (k < 512) ? ldcg4(g_h3s[buf] + m * D_DIM + k)
                         : ldcg4(g_ctxs[buf] + m * VD + (k - 512));
    } else {
        return ldcg4(g_hid + m * D_DIM + k);
    }
}

// LSTM modes use gate-interleaved virtual columns: n -> phys row (n&3)*512 + (n>>2)
template<int MODE>
__device__ __forceinline__ float4 loadB(const KP& p, int n, int k)
{
    if (MODE <= 2) {
        int row = (n & 3) * 512 + (n >> 2);
        if (MODE == 0) return (k < 640) ? ld4(p.w_ih0 + (size_t)row * 640 + k)
                                        : ld4(p.w_hh0 + (size_t)row * 512 + (k - 640));
        if (MODE == 1) return (k < 512) ? ld4(p.w_ih1 + (size_t)row * 512 + k)
                                        : ld4(p.w_hh1 + (size_t)row * 512 + (k - 512));
        return (k < 512) ? ld4(p.w_ih2 + (size_t)row * 512 + k)
                         : ld4(p.w_hh2 + (size_t)row * 512 + (k - 512));
    }
    if (MODE == 3) return ld4(p.p1_w + (size_t)n * 640 + k);
    if (n < VOCAB) return ld4(p.emb + (size_t)n * D_DIM + k);
    return make_float4(0.f, 0.f, 0.f, 0.f);
}

// ---------------------------------------------------------------------------
// LSTM cell combine (last-arriving split block; deterministic ss order)
// ---------------------------------------------------------------------------
template<int MODE, int KSPLIT>
__device__ void lstm_combine(const KP& p, int nt)
{
    const int tid = threadIdx.x;
    const float* bih = (MODE == 0) ? p.b_ih0 : (MODE == 1) ? p.b_ih1 : p.b_ih2;
    const float* bhh = (MODE == 0) ? p.b_hh0 : (MODE == 1) ? p.b_hh1 : p.b_hh2;
    float* c = (MODE == 0) ? g_c1 : (MODE == 1) ? g_c2 : g_c3;
    float* h = (MODE == 0) ? g_h1 : (MODE == 1) ? g_h2 : g_h3;
    const int u0 = nt * 32;
#pragma unroll
    for (int j = 0; j < 4; j++) {
        int pair = tid + j * NTHR;
        int m = pair >> 5, u = u0 + (pair & 31);
        float4 s = make_float4(0.f, 0.f, 0.f, 0.f);
#pragma unroll
        for (int ss = 0; ss < KSPLIT; ss++) {
            float4 v = ldcg4(&g_Gp[((size_t)(ss * BATCH + m)) * 2048 + u * 4]);
            s.x += v.x; s.y += v.y; s.z += v.z; s.w += v.w;
        }
        float gi = s.x + bih[u]        + bhh[u];
        float gf = s.y + bih[512 + u]  + bhh[512 + u];
        float gg = s.z + bih[1024 + u] + bhh[1024 + u];
        float go = s.w + bih[1536 + u] + bhh[1536 + u];
        float si = 1.f / (1.f + expf(-gi));
        float sf = 1.f / (1.f + expf(-gf));
        float so = 1.f / (1.f + expf(-go));
        float cc = sf * __ldcg(&c[m * D_DIM + u]) + si * tanhf(gg);
        c[m * D_DIM + u] = cc;
        h[m * D_DIM + u] = so * tanhf(cc);
    }
}

// hid combine (p1): tile nt covers hid cols n0..n0+127. 2048 float4 / 512 = 4.
template<int KSPLIT>
__device__ void hid_combine(const KP& p, int nt)
{
    const int tid = threadIdx.x;
    const int n0 = nt * 128;
#pragma unroll
    for (int j = 0; j < 4; j++) {
        int item = tid + j * NTHR;
        int m = item >> 5, nq = n0 + (item & 31) * 4;
        float4 v = ld4(p.p1_b + nq);
#pragma unroll
        for (int ss = 0; ss < KSPLIT; ss++) {
            float4 w = ldcg4(&g_Pp[((size_t)(ss * BATCH + m)) * D_DIM + nq]);
            v.x += w.x; v.y += w.y; v.z += w.z; v.w += w.w;
        }
        v.x = (v.x > 0.f) ? v.x : 0.01f * v.x;
        v.y = (v.y > 0.f) ? v.y : 0.01f * v.y;
        v.z = (v.z > 0.f) ? v.z : 0.01f * v.z;
        v.w = (v.w > 0.f) ? v.w : 0.01f * v.w;
        *reinterpret_cast<float4*>(&g_hid[m * D_DIM + nq]) = v;
    }
}

// ---------------------------------------------------------------------------
// GEMM: 64x128 tile, 512 threads, 4x4 thread-tile, 32-deep chunks, prefetch.
// Block indexing via (lb, nb) — partition-local.
// FUSE: 0 none, 1 lstm cell, 2 hid combine.  CNTOFF: counter array offset.
// ---------------------------------------------------------------------------
template<int MODE, int NT, int KSPLIT, int KC, int NCH, int FUSE, int CNTOFF>
__device__ void gemm_phase(const KP& p, Smem& sm, int step, float* out,
                           int lb, int nb, int buf)
{
    constexpr int NTILES = NT * KSPLIT;
    const int tid = threadIdx.x;
    const int ty = tid >> 5, tx = tid & 31;
    const int arow = tid & 63;
    const int akg  = (tid >> 6) * 4;
    const int brow = tid & 127;
    const int bkg  = (tid >> 7) * 4;

    int tok = 0;
    if (MODE == 0) tok = p.inputs[step * BATCH + arow];

    for (int tile = lb; tile < NTILES; tile += nb) {
        const int nt = tile % NT, ks = tile / NT;
        const int n0 = nt * 128, kb = ks * KC;
        float acc[4][4] = {};

        float4 rA  = loadA<MODE>(p, tok, arow, kb + akg, buf);
        float4 rB0 = loadB<MODE>(p, n0 + brow, kb + bkg);
        float4 rB1 = loadB<MODE>(p, n0 + brow, kb + bkg + 16);

#pragma unroll 1
        for (int ch = 0; ch < NCH; ch++) {
            __syncthreads();
            sm.u.g.As[akg + 0][arow] = rA.x;  sm.u.g.As[akg + 1][arow] = rA.y;
            sm.u.g.As[akg + 2][arow] = rA.z;  sm.u.g.As[akg + 3][arow] = rA.w;
            sm.u.g.Bs[bkg + 0][brow] = rB0.x; sm.u.g.Bs[bkg + 1][brow] = rB0.y;
            sm.u.g.Bs[bkg + 2][brow] = rB0.z; sm.u.g.Bs[bkg + 3][brow] = rB0.w;
            sm.u.g.Bs[bkg + 16][brow] = rB1.x; sm.u.g.Bs[bkg + 17][brow] = rB1.y;
            sm.u.g.Bs[bkg + 18][brow] = rB1.z; sm.u.g.Bs[bkg + 19][brow] = rB1.w;
            __syncthreads();
            if (ch + 1 < NCH) {
                int k2 = kb + (ch + 1) * 32;
                rA  = loadA<MODE>(p, tok, arow, k2 + akg, buf);
                rB0 = loadB<MODE>(p, n0 + brow, k2 + bkg);
                rB1 = loadB<MODE>(p, n0 + brow, k2 + bkg + 16);
            }
#pragma unroll 8
            for (int kk = 0; kk < 32; kk++) {
                float4 a4 = *reinterpret_cast<const float4*>(&sm.u.g.As[kk][ty * 4]);
                float4 b4 = *reinterpret_cast<const float4*>(&sm.u.g.Bs[kk][tx * 4]);
                acc[0][0] = fmaf(a4.x, b4.x, acc[0][0]);
                acc[0][1] = fmaf(a4.x, b4.y, acc[0][1]);
                acc[0][2] = fmaf(a4.x, b4.z, acc[0][2]);
                acc[0][3] = fmaf(a4.x, b4.w, acc[0][3]);
                acc[1][0] = fmaf(a4.y, b4.x, acc[1][0]);
                acc[1][1] = fmaf(a4.y, b4.y, acc[1][1]);
                acc[1][2] = fmaf(a4.y, b4.z, acc[1][2]);
                acc[1][3] = fmaf(a4.y, b4.w, acc[1][3]);
                acc[2][0] = fmaf(a4.z, b4.x, acc[2][0]);
                acc[2][1] = fmaf(a4.z, b4.y, acc[2][1]);
                acc[2][2] = fmaf(a4.z, b4.z, acc[2][2]);
                acc[2][3] = fmaf(a4.z, b4.w, acc[2][3]);
                acc[3][0] = fmaf(a4.w, b4.x, acc[3][0]);
                acc[3][1] = fmaf(a4.w, b4.y, acc[3][1]);
                acc[3][2] = fmaf(a4.w, b4.z, acc[3][2]);
                acc[3][3] = fmaf(a4.w, b4.w, acc[3][3]);
            }
        }

        // ---- epilogue: store partials ----
        if (MODE == 4) {
            const bool edge = (n0 + 127 >= VOCAB);
#pragma unroll
            for (int i = 0; i < 4; i++) {
                size_t row = ((size_t)(ks * BATCH + ty * 4 + i)) * LPLD;
                int n = n0 + tx * 4;
                if (!edge) {
                    *reinterpret_cast<float4*>(&out[row + n]) =
                        make_float4(acc[i][0], acc[i][1], acc[i][2], acc[i][3]);
                } else {
#pragma unroll
                    for (int j = 0; j < 4; j++)
                        if (n + j < VOCAB) out[row + n + j] = acc[i][j];
                }
            }
        } else {
            const int NNout = (MODE == 3) ? 512 : 2048;
#pragma unroll
            for (int i = 0; i < 4; i++)
                *reinterpret_cast<float4*>(
                    &out[((size_t)(ks * BATCH + ty * 4 + i)) * NNout + n0 + tx * 4]) =
                    make_float4(acc[i][0], acc[i][1], acc[i][2], acc[i][3]);
        }

        if (FUSE != 0) {
            __syncthreads();
            if (tid == 0) {
                __threadfence();
                sm.flag = (atomicAdd(&g_cnt[CNTOFF + nt], 1u) == KSPLIT - 1);
            }
            __syncthreads();
            if (sm.flag) {
                __threadfence();
                if (FUSE == 1) lstm_combine<MODE, KSPLIT>(p, nt);
                else           hid_combine<KSPLIT>(p, nt);
                if (tid == 0) g_cnt[CNTOFF + nt] = 0;
            }
        }
    }
}

// ---------------------------------------------------------------------------
// Spine: cell3 + query + attention + context + snapshot.  Blocks 0..63.
// ---------------------------------------------------------------------------
__device__ void attn_phase(const KP& p, Smem& sm, bool with_q, float* attn_out,
                           int buf, int t, unsigned bbase)
{
    if (blockIdx.x >= BATCH) return;
    const int b = blockIdx.x, tid = threadIdx.x;

    // wait until branch has consumed the snapshot buffer we're about to overwrite
    if (buf >= 0 && t >= 2) {
        if (tid == 0) {
            while (*(volatile unsigned*)&g_bdone < bbase + (unsigned)(t - 1)) { }
            __threadfence();
        }
        __syncthreads();
    }

    if (with_q) {
        float hh = __ldcg(&g_h3[b * D_DIM + tid]);
        sm.u.a.h3s[tid] = hh;
        if (buf >= 0) g_h3s[buf][b * D_DIM + tid] = hh;
        __syncthreads();
        {
            int n = tid >> 2, part = tid & 3;
            const float4* wp = reinterpret_cast<const float4*>(p.q_w + (size_t)n * D_DIM + part * 128);
            const float4* hp = reinterpret_cast<const float4*>(sm.u.a.h3s + part * 128);
            float s = 0.f;
#pragma unroll
            for (int i = 0; i < 32; i++) {
                float4 wv = wp[i], hv = hp[i];
                s = fmaf(wv.x, hv.x, s); s = fmaf(wv.y, hv.y, s);
                s = fmaf(wv.z, hv.z, s); s = fmaf(wv.w, hv.w, s);
            }
            s += __shfl_down_sync(0xffffffffu, s, 1);
            s += __shfl_down_sync(0xffffffffu, s, 2);
            if (part == 0) sm.u.a.q[n] = s + p.q_b[n];
        }
        __syncthreads();
    } else {
        if (tid < KD) sm.u.a.q[tid] = p.q_b[tid];
        __syncthreads();
    }

    const int L = p.ulen[b];
    float e;
    {
        const float4* kp = reinterpret_cast<const float4*>(p.keys + ((size_t)tid * BATCH + b) * KD);
        const float4* qp = reinterpret_cast<const float4*>(sm.u.a.q);
        float s = 0.f;
#pragma unroll
        for (int i = 0; i < KD / 4; i++) {
            float4 kv = kp[i], qv = qp[i];
            s = fmaf(kv.x, qv.x, s); s = fmaf(kv.y, qv.y, s);
            s = fmaf(kv.z, qv.z, s); s = fmaf(kv.w, qv.w, s);
        }
        e = (tid < L) ? s : -10000.0f;
    }
    sm.u.a.red[tid] = e;
    __syncthreads();
    for (int s = 256; s > 0; s >>= 1) {
        if (tid < s) sm.u.a.red[tid] = fmaxf(sm.u.a.red[tid], sm.u.a.red[tid + s]);
        __syncthreads();
    }
    const float emax = sm.u.a.red[0];
    __syncthreads();

    float x = (tid < L) ? expf(e - emax) : 0.f;
    sm.u.a.red[tid] = x;
    __syncthreads();
    for (int s = 256; s > 0; s >>= 1) {
        if (tid < s) sm.u.a.red[tid] += sm.u.a.red[tid + s];
        __syncthreads();
    }
    const float inv = 1.f / sm.u.a.red[0];
    __syncthreads();

    float a = x * inv;
    sm.u.a.arr[tid] = a;
    attn_out[(size_t)b * TENC + tid] = a;
    __syncthreads();

    {
        int v = tid & 127, c4 = tid >> 7;
        float s = 0.f;
        int tb = c4 * 128;
#pragma unroll 8
        for (int tt = tb; tt < tb + 128; tt++)
            s = fmaf(sm.u.a.arr[tt], p.values[((size_t)tt * BATCH + b) * VD + v], s);
        sm.u.a.ps[c4][v] = s;
    }
    __syncthreads();
    if (tid < VD) {
        float cv = sm.u.a.ps[0][tid] + sm.u.a.ps[1][tid]
                 + sm.u.a.ps[2][tid] + sm.u.a.ps[3][tid];
        g_ctx[b * VD + tid] = cv;
        if (buf >= 0) g_ctxs[buf][b * VD + tid] = cv;
    }
}

// ---------------------------------------------------------------------------
// Threefry-2x32 + logits combine + Gumbel argmax (branch blocks lb 0..63)
// ---------------------------------------------------------------------------
__device__ __forceinline__ void tf2x32(uint32_t k0, uint32_t k1, uint32_t x0, uint32_t x1,
                                       uint32_t& o0, uint32_t& o1)
{
    uint32_t ks2 = k0 ^ k1 ^ 0x1BD11BDAu;
    x0 += k0; x1 += k1;
#define TFR(r) { x0 += x1; x1 = (x1 << (r)) | (x1 >> (32 - (r))); x1 ^= x0; }
    TFR(13) TFR(15) TFR(26) TFR(6)   x0 += k1;  x1 += ks2 + 1u;
    TFR(17) TFR(29) TFR(16) TFR(24)  x0 += ks2; x1 += k0 + 2u;
    TFR(13) TFR(15) TFR(26) TFR(6)   x0 += k0;  x1 += k1 + 3u;
    TFR(17) TFR(29) TFR(16) TFR(24)  x0 += k1;  x1 += ks2 + 4u;
    TFR(13) TFR(15) TFR(26) TFR(6)   x0 += ks2; x1 += k0 + 5u;
#undef TFR
    o0 = x0; o1 = x1;
}

__device__ void sample_phase(const KP& p, Smem& sm, int step, int lb)
{
    if (lb >= BATCH) return;
    const int b = lb, tid = threadIdx.x;
    uint32_t fk0, fk1;
    tf2x32(0u, 1u, 0u, (uint32_t)step, fk0, fk1);

    float* outl = p.out_logits + ((size_t)step * BATCH + b) * VOCAB;
    float best = -__int_as_float(0x7f800000);
    int bidx = 0;
    for (int v = tid; v < VOCAB; v += NTHR) {
        float lg = p.p2_b[v];
#pragma unroll
        for (int ss = 0; ss < LKS; ss++)
            lg += __ldcg(&g_Lp[((size_t)(ss * BATCH + b)) * LPLD + v]);
        outl[v] = lg;
        uint32_t o0, o1;
        tf2x32(fk0, fk1, 0u, (uint32_t)(b * VOCAB + v), o0, o1);
        uint32_t bits = o0 ^ o1;
        float u = __uint_as_float((bits >> 9) | 0x3f800000u) - 1.0f;
        float gmb = -logf(1e-10f - logf(u + 1e-10f));
        float val = lg + gmb;
        if (val > best) { best = val; bidx = v; }
    }
    sm.u.s.sv[tid] = best; sm.u.s.si[tid] = bidx;
    __syncthreads();
    for (int s = 256; s > 0; s >>= 1) {
        if (tid < s) {
            if (sm.u.s.sv[tid + s] > sm.u.s.sv[tid] ||
                (sm.u.s.sv[tid + s] == sm.u.s.sv[tid] && sm.u.s.si[tid + s] < sm.u.s.si[tid])) {
                sm.u.s.sv[tid] = sm.u.s.sv[tid + s]; sm.u.s.si[tid] = sm.u.s.si[tid + s];
            }
        }
        __syncthreads();
    }
    if (tid == 0) p.out_gen[step * BATCH + b] = (float)sm.u.s.si[0];
    __syncthreads();
}

// ---------------------------------------------------------------------------
// The megakernel — spine/branch partition pipeline
// ---------------------------------------------------------------------------
__global__ __launch_bounds__(NTHR, 2) void mega_kernel(KP p)
{
    __shared__ Smem sm;
    const int tid = threadIdx.x;
    const int bid = blockIdx.x;
    const int NSP = p.nsp;
    const int NBR = (int)gridDim.x - NSP;

    // entry: read monotonic bases BEFORE any writes
    const unsigned sbase = *(volatile unsigned*)&g_sready;
    const unsigned bbase = *(volatile unsigned*)&g_bdone;

    for (int i = bid * NTHR + tid; i < BATCH * D_DIM; i += gridDim.x * NTHR) {
        g_h1[i] = 0.f; g_c1[i] = 0.f;
        g_h2[i] = 0.f; g_c2[i] = 0.f;
        g_h3[i] = 0.f; g_c3[i] = 0.f;
        if (i < BATCH * VD) g_ctx[i] = 0.f;
    }
    full_sync();

    if (bid < NSP) {
        // ================= SPINE: recurrent LSTM chain + attention ==========
        attn_phase(p, sm, false, g_attn_scratch, -1, -1, bbase);   // ctx0
        part_sync(&g_sbar[0], &g_sbar[16], (unsigned)NSP);

        for (int t = 0; t < TDEC; t++) {
            gemm_phase<0, 16, 9, 128, 4, 1, 0>(p, sm, t, g_Gp, bid, NSP, 0);   // lstm0+cell
            part_sync(&g_sbar[0], &g_sbar[16], (unsigned)NSP);
            gemm_phase<1, 16, 8, 128, 4, 1, 0>(p, sm, t, g_Gp, bid, NSP, 0);   // lstm1+cell
            part_sync(&g_sbar[0], &g_sbar[16], (unsigned)NSP);
            gemm_phase<2, 16, 8, 128, 4, 1, 0>(p, sm, t, g_Gp, bid, NSP, 0);   // lstm2+cell
            part_sync(&g_sbar[0], &g_sbar[16], (unsigned)NSP);
            attn_phase(p, sm, true, p.out_attn + (size_t)t * BATCH * TENC,
                       t & 1, t, bbase);
            part_sync(&g_sbar[0], &g_sbar[16], (unsigned)NSP);
            if (bid == 0 && tid == 0)
                atomicExch(&g_sready, sbase + (unsigned)(t + 1));   // publish h3/ctx(t)
        }
    } else {
        // ================= BRANCH: p1 -> logits -> sample (lag 1) ===========
        const int lb = bid - NSP;
        for (int t = 0; t < TDEC; t++) {
            if (tid == 0) {
                while (*(volatile unsigned*)&g_sready < sbase + (unsigned)(t + 1)) { }
                __threadfence();
            }
            __syncthreads();

            gemm_phase<3, 4, 20, 32, 1, 2, 16>(p, sm, t, g_Pp, lb, NBR, t & 1); // p1+hid
            part_sync(&g_bbar[0], &g_bbar[16], (unsigned)NBR);
            gemm_phase<4, 79, LKS, 128, 4, 0, 0>(p, sm, t, g_Lp, lb, NBR, 0);   // logits
            part_sync(&g_bbar[0], &g_bbar[16], (unsigned)NBR);
            sample_phase(p, sm, t, lb);
            part_sync(&g_bbar[0], &g_bbar[16], (unsigned)NBR);
            if (lb == 0 && tid == 0)
                atomicExch(&g_bdone, bbase + (unsigned)(t + 1));
        }
    }
}

// ---------------------------------------------------------------------------
// Host launcher — single graph node
// ---------------------------------------------------------------------------
extern "C" void kernel_launch(void* const* d_in, const int* in_sizes, int n_in,
                              void* d_out, int out_size)
{
    (void)in_sizes; (void)n_in;
    KP p;
    p.inputs = (const int*)  d_in[0];
    p.keys   = (const float*)d_in[2];
    p.values = (const float*)d_in[3];
    p.ulen   = (const int*)  d_in[4];
    p.emb    = (const float*)d_in[5];
    p.w_ih0 = (const float*)d_in[6];  p.w_hh0 = (const float*)d_in[7];
    p.b_ih0 = (const float*)d_in[8];  p.b_hh0 = (const float*)d_in[9];
    p.w_ih1 = (const float*)d_in[10]; p.w_hh1 = (const float*)d_in[11];
    p.b_ih1 = (const float*)d_in[12]; p.b_hh1 = (const float*)d_in[13];
    p.w_ih2 = (const float*)d_in[14]; p.w_hh2 = (const float*)d_in[15];
    p.b_ih2 = (const float*)d_in[16]; p.b_hh2 = (const float*)d_in[17];
    p.q_w  = (const float*)d_in[18];  p.q_b  = (const float*)d_in[19];
    p.p1_w = (const float*)d_in[20];  p.p1_b = (const float*)d_in[21];
    p.p2_b = (const float*)d_in[22];

    float* out = (float*)d_out;
    const size_t L_LOG = (size_t)TDEC * BATCH * VOCAB;
    const size_t L_ATT = (size_t)TDEC * BATCH * TENC;
    const size_t TOTAL = L_LOG + L_ATT + (size_t)TDEC * BATCH;
    const bool full = (size_t)out_size >= TOTAL;

    void* vp;
    cudaGetSymbolAddress(&vp, g_attn_scratch);
    float* pAS = (float*)vp;
    cudaGetSymbolAddress(&vp, g_gen_scratch);
    float* pGS = (float*)vp;

    p.out_logits = out;
    p.out_attn   = full ? out + L_LOG         : pAS;
    p.out_gen    = full ? out + L_LOG + L_ATT : pGS;

    int dev = 0, sms = 0;
    cudaGetDevice(&dev);
    cudaDeviceGetAttribute(&sms, cudaDevAttrMultiProcessorCount, dev);
    if (sms < 64) sms = 64;

    int occ = 1;
    cudaOccupancyMaxActiveBlocksPerMultiprocessor(&occ, mega_kernel, NTHR, 0);
    if (occ < 1) occ = 1;
    if (occ > 2) occ = 2;

    int grid = sms * occ;
    int nbr = grid / 2;
    if (nbr < 64) nbr = 64;           // sampler needs 64 branch blocks
    p.nsp = grid - nbr;               // attention needs >=64 spine blocks

    mega_kernel<<<grid, NTHR>>>(p);
}

// round 12
// speedup vs baseline: 1.7340x; 1.0115x over previous
#include <cuda_runtime.h>
#include <math.h>
#include <stdint.h>
#include <stddef.h>

#define D_DIM   512
#define KD      128
#define VD      128
#define VOCAB   10001
#define BATCH   64
#define TDEC    192
#define TENC    512
#define NTHR    512
#define LPLD    10016          // padded row stride for logits partials
#define LKS     8              // logits K-split

// ---------------------------------------------------------------------------
// Persistent state / scratch (device globals; no allocation allowed)
// ---------------------------------------------------------------------------
__device__ __align__(16) float g_h1[BATCH * D_DIM], g_c1[BATCH * D_DIM];
__device__ __align__(16) float g_h2[BATCH * D_DIM], g_c2[BATCH * D_DIM];
__device__ __align__(16) float g_h3[BATCH * D_DIM], g_c3[BATCH * D_DIM];
__device__ __align__(16) float g_ctx[BATCH * VD];
__device__ __align__(16) float g_hid[BATCH * D_DIM];
__device__ __align__(16) float g_h3s[2][BATCH * D_DIM];   // snapshots for branch
__device__ __align__(16) float g_ctxs[2][BATCH * VD];
__device__ __align__(16) float g_Gp[9 * BATCH * 2048];    // LSTM gate partials
__device__ __align__(16) float g_Pp[20 * BATCH * D_DIM];  // p1 partials
__device__ __align__(16) float g_Lp[LKS * BATCH * LPLD];  // logits partials
__device__ __align__(16) float g_attn_scratch[BATCH * TENC];
__device__ __align__(16) float g_gen_scratch [TDEC * BATCH];
__device__ unsigned g_cnt[32];             // per-n-tile split counters
__device__ unsigned g_bar_count, g_bar_gen;                // full-grid barrier
__device__ __align__(128) unsigned g_sbar[32];             // spine barrier [0]=cnt [16]=gen
__device__ __align__(128) unsigned g_bbar[32];             // branch barrier
__device__ __align__(128) unsigned g_sready;               // steps published by spine
__device__ __align__(128) unsigned g_bdone;                // snapshots consumed by branch

struct KP {
    const int*   inputs;
    const float* keys;   const float* values; const int* ulen;
    const float* emb;
    const float* w_ih0; const float* w_hh0; const float* b_ih0; const float* b_hh0;
    const float* w_ih1; const float* w_hh1; const float* b_ih1; const float* b_hh1;
    const float* w_ih2; const float* w_hh2; const float* b_ih2; const float* b_hh2;
    const float* q_w;  const float* q_b;
    const float* p1_w; const float* p1_b; const float* p2_b;
    float* out_logits; float* out_attn; float* out_gen;
    int nsp;           // spine block count; branch = grid - nsp
};

struct __align__(16) Smem {
    union {
        struct { float As[32][64]; float Bs[32][128]; } g;    // 8KB + 16KB
        struct { float h3s[D_DIM]; float q[KD]; float arr[TENC];
                 float red[NTHR]; float ps[4][VD]; } a;
        struct { float sv[NTHR]; int si[NTHR]; } s;
    } u;
    int flag;
};

// ---------------------------------------------------------------------------
// Barriers
// ---------------------------------------------------------------------------
__device__ __forceinline__ void full_sync()
{
    __syncthreads();
    if (threadIdx.x == 0) {
        __threadfence();
        unsigned my = *((volatile unsigned*)&g_bar_gen);
        if (atomicAdd(&g_bar_count, 1u) == gridDim.x - 1) {
            atomicExch(&g_bar_count, 0u);
            __threadfence();
            atomicAdd(&g_bar_gen, 1u);
        } else {
            while (*((volatile unsigned*)&g_bar_gen) == my) { }
        }
        __threadfence();
    }
    __syncthreads();
}

__device__ __forceinline__ void part_sync(unsigned* cnt, unsigned* gen, unsigned n)
{
    __syncthreads();
    if (threadIdx.x == 0) {
        __threadfence();
        unsigned my = *((volatile unsigned*)gen);
        if (atomicAdd(cnt, 1u) == n - 1) {
            atomicExch(cnt, 0u);
            __threadfence();
            atomicAdd(gen, 1u);
        } else {
            while (*((volatile unsigned*)gen) == my) { }
        }
        __threadfence();
    }
    __syncthreads();
}

// ---------------------------------------------------------------------------
// Virtual-operand loaders.  Mutable state via __ldcg (L2-coherent).
// ---------------------------------------------------------------------------
__device__ __forceinline__ float4 ld4(const float* p) { return *reinterpret_cast<const float4*>(p); }
__device__ __forceinline__ float4 ldcg4(const float* p) { return __ldcg(reinterpret_cast<const float4*>(p)); }

template<int MODE>
__device__ __forceinline__ float4 loadA(const KP& p, int tok, int m, int k, int buf)
{
    if (MODE == 0) {
        if (k < 512)      return ld4(p.emb + (size_t)tok * D_DIM + k);
        else if (k < 640) return ldcg4(g_ctx + m * VD + (k - 512));
        else              return ldcg4(g_h1 + m * D_DIM + (k - 640));
    } else if (MODE == 1) {
        return (k < 512) ? ldcg4(g_h1 + m * D_DIM + k) : ldcg4(g_h2 + m * D_DIM + (k - 512));
    } else if (MODE == 2) {
        return (k < 512) ? ldcg4(g_h2 + m * D_DIM + k) : ldcg4(g_h3 + m * D_DIM + (k - 512));
    } else if (MODE == 3) {
        return (k < 512) ? ldcg4(g_h3s[buf] + m * D_DIM + k)
                         : ldcg4(g_ctxs[buf] + m * VD + (k - 512));
    } else {
        return ldcg4(g_hid + m * D_DIM + k);
    }
}

// LSTM modes use gate-interleaved virtual columns: n -> phys row (n&3)*512 + (n>>2)
template<int MODE>
__device__ __forceinline__ float4 loadB(const KP& p, int n, int k)
{
    if (MODE <= 2) {
        int row = (n & 3) * 512 + (n >> 2);
        if (MODE == 0) return (k < 640) ? ld4(p.w_ih0 + (size_t)row * 640 + k)
                                        : ld4(p.w_hh0 + (size_t)row * 512 + (k - 640));
        if (MODE == 1) return (k < 512) ? ld4(p.w_ih1 + (size_t)row * 512 + k)
                                        : ld4(p.w_hh1 + (size_t)row * 512 + (k - 512));
        return (k < 512) ? ld4(p.w_ih2 + (size_t)row * 512 + k)
                         : ld4(p.w_hh2 + (size_t)row * 512 + (k - 512));
    }
    if (MODE == 3) return ld4(p.p1_w + (size_t)n * 640 + k);
    if (n < VOCAB) return ld4(p.emb + (size_t)n * D_DIM + k);
    return make_float4(0.f, 0.f, 0.f, 0.f);
}

// ---------------------------------------------------------------------------
// LSTM cell combine (last-arriving split block; deterministic ss order)
// ---------------------------------------------------------------------------
template<int MODE, int KSPLIT>
__device__ void lstm_combine(const KP& p, int nt)
{
    const int tid = threadIdx.x;
    const float* bih = (MODE == 0) ? p.b_ih0 : (MODE == 1) ? p.b_ih1 : p.b_ih2;
    const float* bhh = (MODE == 0) ? p.b_hh0 : (MODE == 1) ? p.b_hh1 : p.b_hh2;
    float* c = (MODE == 0) ? g_c1 : (MODE == 1) ? g_c2 : g_c3;
    float* h = (MODE == 0) ? g_h1 : (MODE == 1) ? g_h2 : g_h3;
    const int u0 = nt * 32;
#pragma unroll
    for (int j = 0; j < 4; j++) {
        int pair = tid + j * NTHR;
        int m = pair >> 5, u = u0 + (pair & 31);
        float4 s = make_float4(0.f, 0.f, 0.f, 0.f);
#pragma unroll
        for (int ss = 0; ss < KSPLIT; ss++) {
            float4 v = ldcg4(&g_Gp[((size_t)(ss * BATCH + m)) * 2048 + u * 4]);
            s.x += v.x; s.y += v.y; s.z += v.z; s.w += v.w;
        }
        float gi = s.x + bih[u]        + bhh[u];
        float gf = s.y + bih[512 + u]  + bhh[512 + u];
        float gg = s.z + bih[1024 + u] + bhh[1024 + u];
        float go = s.w + bih[1536 + u] + bhh[1536 + u];
        float si = 1.f / (1.f + expf(-gi));
        float sf = 1.f / (1.f + expf(-gf));
        float so = 1.f / (1.f + expf(-go));
        float cc = sf * __ldcg(&c[m * D_DIM + u]) + si * tanhf(gg);
        c[m * D_DIM + u] = cc;
        h[m * D_DIM + u] = so * tanhf(cc);
    }
}

// hid combine (p1): tile nt covers hid cols n0..n0+127. 2048 float4 / 512 = 4.
template<int KSPLIT>
__device__ void hid_combine(const KP& p, int nt)
{
    const int tid = threadIdx.x;
    const int n0 = nt * 128;
#pragma unroll
    for (int j = 0; j < 4; j++) {
        int item = tid + j * NTHR;
        int m = item >> 5, nq = n0 + (item & 31) * 4;
        float4 v = ld4(p.p1_b + nq);
#pragma unroll
        for (int ss = 0; ss < KSPLIT; ss++) {
            float4 w = ldcg4(&g_Pp[((size_t)(ss * BATCH + m)) * D_DIM + nq]);
            v.x += w.x; v.y += w.y; v.z += w.z; v.w += w.w;
        }
        v.x = (v.x > 0.f) ? v.x : 0.01f * v.x;
        v.y = (v.y > 0.f) ? v.y : 0.01f * v.y;
        v.z = (v.z > 0.f) ? v.z : 0.01f * v.z;
        v.w = (v.w > 0.f) ? v.w : 0.01f * v.w;
        *reinterpret_cast<float4*>(&g_hid[m * D_DIM + nq]) = v;
    }
}

// ---------------------------------------------------------------------------
// GEMM: 64x128 tile, 512 threads, 4x4 thread-tile, 32-deep chunks, prefetch.
// Block indexing via (lb, nb) — partition-local.
// FUSE: 0 none, 1 lstm cell, 2 hid combine.  CNTOFF: counter array offset.
// ---------------------------------------------------------------------------
template<int MODE, int NT, int KSPLIT, int KC, int NCH, int FUSE, int CNTOFF>
__device__ void gemm_phase(const KP& p, Smem& sm, int step, float* out,
                           int lb, int nb, int buf)
{
    constexpr int NTILES = NT * KSPLIT;
    const int tid = threadIdx.x;
    const int ty = tid >> 5, tx = tid & 31;
    const int arow = tid & 63;
    const int akg  = (tid >> 6) * 4;
    const int brow = tid & 127;
    const int bkg  = (tid >> 7) * 4;

    int tok = 0;
    if (MODE == 0) tok = p.inputs[step * BATCH + arow];

    for (int tile = lb; tile < NTILES; tile += nb) {
        const int nt = tile % NT, ks = tile / NT;
        const int n0 = nt * 128, kb = ks * KC;
        float acc[4][4] = {};

        float4 rA  = loadA<MODE>(p, tok, arow, kb + akg, buf);
        float4 rB0 = loadB<MODE>(p, n0 + brow, kb + bkg);
        float4 rB1 = loadB<MODE>(p, n0 + brow, kb + bkg + 16);

#pragma unroll 1
        for (int ch = 0; ch < NCH; ch++) {
            __syncthreads();
            sm.u.g.As[akg + 0][arow] = rA.x;  sm.u.g.As[akg + 1][arow] = rA.y;
            sm.u.g.As[akg + 2][arow] = rA.z;  sm.u.g.As[akg + 3][arow] = rA.w;
            sm.u.g.Bs[bkg + 0][brow] = rB0.x; sm.u.g.Bs[bkg + 1][brow] = rB0.y;
            sm.u.g.Bs[bkg + 2][brow] = rB0.z; sm.u.g.Bs[bkg + 3][brow] = rB0.w;
            sm.u.g.Bs[bkg + 16][brow] = rB1.x; sm.u.g.Bs[bkg + 17][brow] = rB1.y;
            sm.u.g.Bs[bkg + 18][brow] = rB1.z; sm.u.g.Bs[bkg + 19][brow] = rB1.w;
            __syncthreads();
            if (ch + 1 < NCH) {
                int k2 = kb + (ch + 1) * 32;
                rA  = loadA<MODE>(p, tok, arow, k2 + akg, buf);
                rB0 = loadB<MODE>(p, n0 + brow, k2 + bkg);
                rB1 = loadB<MODE>(p, n0 + brow, k2 + bkg + 16);
            }
#pragma unroll 8
            for (int kk = 0; kk < 32; kk++) {
                float4 a4 = *reinterpret_cast<const float4*>(&sm.u.g.As[kk][ty * 4]);
                float4 b4 = *reinterpret_cast<const float4*>(&sm.u.g.Bs[kk][tx * 4]);
                acc[0][0] = fmaf(a4.x, b4.x, acc[0][0]);
                acc[0][1] = fmaf(a4.x, b4.y, acc[0][1]);
                acc[0][2] = fmaf(a4.x, b4.z, acc[0][2]);
                acc[0][3] = fmaf(a4.x, b4.w, acc[0][3]);
                acc[1][0] = fmaf(a4.y, b4.x, acc[1][0]);
                acc[1][1] = fmaf(a4.y, b4.y, acc[1][1]);
                acc[1][2] = fmaf(a4.y, b4.z, acc[1][2]);
                acc[1][3] = fmaf(a4.y, b4.w, acc[1][3]);
                acc[2][0] = fmaf(a4.z, b4.x, acc[2][0]);
                acc[2][1] = fmaf(a4.z, b4.y, acc[2][1]);
                acc[2][2] = fmaf(a4.z, b4.z, acc[2][2]);
                acc[2][3] = fmaf(a4.z, b4.w, acc[2][3]);
                acc[3][0] = fmaf(a4.w, b4.x, acc[3][0]);
                acc[3][1] = fmaf(a4.w, b4.y, acc[3][1]);
                acc[3][2] = fmaf(a4.w, b4.z, acc[3][2]);
                acc[3][3] = fmaf(a4.w, b4.w, acc[3][3]);
            }
        }

        // ---- epilogue: store partials ----
        if (MODE == 4) {
            const bool edge = (n0 + 127 >= VOCAB);
#pragma unroll
            for (int i = 0; i < 4; i++) {
                size_t row = ((size_t)(ks * BATCH + ty * 4 + i)) * LPLD;
                int n = n0 + tx * 4;
                if (!edge) {
                    *reinterpret_cast<float4*>(&out[row + n]) =
                        make_float4(acc[i][0], acc[i][1], acc[i][2], acc[i][3]);
                } else {
#pragma unroll
                    for (int j = 0; j < 4; j++)
                        if (n + j < VOCAB) out[row + n + j] = acc[i][j];
                }
            }
        } else {
            const int NNout = (MODE == 3) ? 512 : 2048;
#pragma unroll
            for (int i = 0; i < 4; i++)
                *reinterpret_cast<float4*>(
                    &out[((size_t)(ks * BATCH + ty * 4 + i)) * NNout + n0 + tx * 4]) =
                    make_float4(acc[i][0], acc[i][1], acc[i][2], acc[i][3]);
        }

        if (FUSE != 0) {
            __syncthreads();
            if (tid == 0) {
                __threadfence();
                sm.flag = (atomicAdd(&g_cnt[CNTOFF + nt], 1u) == KSPLIT - 1);
            }
            __syncthreads();
            if (sm.flag) {
                __threadfence();
                if (FUSE == 1) lstm_combine<MODE, KSPLIT>(p, nt);
                else           hid_combine<KSPLIT>(p, nt);
                if (tid == 0) g_cnt[CNTOFF + nt] = 0;
            }
        }
    }
}

// ---------------------------------------------------------------------------
// Spine: cell3 + query + attention + context + snapshot.  Blocks 0..63.
// ---------------------------------------------------------------------------
__device__ void attn_phase(const KP& p, Smem& sm, bool with_q, float* attn_out,
                           int buf, int t, unsigned bbase)
{
    if (blockIdx.x >= BATCH) return;
    const int b = blockIdx.x, tid = threadIdx.x;

    // wait until branch has consumed (p1 done) the snapshot buffer we overwrite
    if (buf >= 0 && t >= 2) {
        if (tid == 0) {
            while (*(volatile unsigned*)&g_bdone < bbase + (unsigned)(t - 1)) { }
            __threadfence();
        }
        __syncthreads();
    }

    if (with_q) {
        float hh = __ldcg(&g_h3[b * D_DIM + tid]);
        sm.u.a.h3s[tid] = hh;
        if (buf >= 0) g_h3s[buf][b * D_DIM + tid] = hh;
        __syncthreads();
        {
            int n = tid >> 2, part = tid & 3;
            const float4* wp = reinterpret_cast<const float4*>(p.q_w + (size_t)n * D_DIM + part * 128);
            const float4* hp = reinterpret_cast<const float4*>(sm.u.a.h3s + part * 128);
            float s = 0.f;
#pragma unroll
            for (int i = 0; i < 32; i++) {
                float4 wv = wp[i], hv = hp[i];
                s = fmaf(wv.x, hv.x, s); s = fmaf(wv.y, hv.y, s);
                s = fmaf(wv.z, hv.z, s); s = fmaf(wv.w, hv.w, s);
            }
            s += __shfl_down_sync(0xffffffffu, s, 1);
            s += __shfl_down_sync(0xffffffffu, s, 2);
            if (part == 0) sm.u.a.q[n] = s + p.q_b[n];
        }
        __syncthreads();
    } else {
        if (tid < KD) sm.u.a.q[tid] = p.q_b[tid];
        __syncthreads();
    }

    const int L = p.ulen[b];
    float e;
    {
        const float4* kp = reinterpret_cast<const float4*>(p.keys + ((size_t)tid * BATCH + b) * KD);
        const float4* qp = reinterpret_cast<const float4*>(sm.u.a.q);
        float s = 0.f;
#pragma unroll
        for (int i = 0; i < KD / 4; i++) {
            float4 kv = kp[i], qv = qp[i];
            s = fmaf(kv.x, qv.x, s); s = fmaf(kv.y, qv.y, s);
            s = fmaf(kv.z, qv.z, s); s = fmaf(kv.w, qv.w, s);
        }
        e = (tid < L) ? s : -10000.0f;
    }
    sm.u.a.red[tid] = e;
    __syncthreads();
    for (int s = 256; s > 0; s >>= 1) {
        if (tid < s) sm.u.a.red[tid] = fmaxf(sm.u.a.red[tid], sm.u.a.red[tid + s]);
        __syncthreads();
    }
    const float emax = sm.u.a.red[0];
    __syncthreads();

    float x = (tid < L) ? expf(e - emax) : 0.f;
    sm.u.a.red[tid] = x;
    __syncthreads();
    for (int s = 256; s > 0; s >>= 1) {
        if (tid < s) sm.u.a.red[tid] += sm.u.a.red[tid + s];
        __syncthreads();
    }
    const float inv = 1.f / sm.u.a.red[0];
    __syncthreads();

    float a = x * inv;
    sm.u.a.arr[tid] = a;
    attn_out[(size_t)b * TENC + tid] = a;
    __syncthreads();

    {
        int v = tid & 127, c4 = tid >> 7;
        float s = 0.f;
        int tb = c4 * 128;
#pragma unroll 8
        for (int tt = tb; tt < tb + 128; tt++)
            s = fmaf(sm.u.a.arr[tt], p.values[((size_t)tt * BATCH + b) * VD + v], s);
        sm.u.a.ps[c4][v] = s;
    }
    __syncthreads();
    if (tid < VD) {
        float cv = sm.u.a.ps[0][tid] + sm.u.a.ps[1][tid]
                 + sm.u.a.ps[2][tid] + sm.u.a.ps[3][tid];
        g_ctx[b * VD + tid] = cv;
        if (buf >= 0) g_ctxs[buf][b * VD + tid] = cv;
    }
}

// ---------------------------------------------------------------------------
// Threefry-2x32 + logits combine + Gumbel argmax.  sb = batch index or -1.
// ---------------------------------------------------------------------------
__device__ __forceinline__ void tf2x32(uint32_t k0, uint32_t k1, uint32_t x0, uint32_t x1,
                                       uint32_t& o0, uint32_t& o1)
{
    uint32_t ks2 = k0 ^ k1 ^ 0x1BD11BDAu;
    x0 += k0; x1 += k1;
#define TFR(r) { x0 += x1; x1 = (x1 << (r)) | (x1 >> (32 - (r))); x1 ^= x0; }
    TFR(13) TFR(15) TFR(26) TFR(6)   x0 += k1;  x1 += ks2 + 1u;
    TFR(17) TFR(29) TFR(16) TFR(24)  x0 += ks2; x1 += k0 + 2u;
    TFR(13) TFR(15) TFR(26) TFR(6)   x0 += k0;  x1 += k1 + 3u;
    TFR(17) TFR(29) TFR(16) TFR(24)  x0 += k1;  x1 += ks2 + 4u;
    TFR(13) TFR(15) TFR(26) TFR(6)   x0 += ks2; x1 += k0 + 5u;
#undef TFR
    o0 = x0; o1 = x1;
}

__device__ void sample_phase(const KP& p, Smem& sm, int step, int sb)
{
    if (sb < 0 || sb >= BATCH) return;
    const int b = sb, tid = threadIdx.x;
    uint32_t fk0, fk1;
    tf2x32(0u, 1u, 0u, (uint32_t)step, fk0, fk1);

    float* outl = p.out_logits + ((size_t)step * BATCH + b) * VOCAB;
    float best = -__int_as_float(0x7f800000);
    int bidx = 0;
    for (int v = tid; v < VOCAB; v += NTHR) {
        float lg = p.p2_b[v];
#pragma unroll
        for (int ss = 0; ss < LKS; ss++)
            lg += __ldcg(&g_Lp[((size_t)(ss * BATCH + b)) * LPLD + v]);
        outl[v] = lg;
        uint32_t o0, o1;
        tf2x32(fk0, fk1, 0u, (uint32_t)(b * VOCAB + v), o0, o1);
        uint32_t bits = o0 ^ o1;
        float u = __uint_as_float((bits >> 9) | 0x3f800000u) - 1.0f;
        float gmb = -logf(1e-10f - logf(u + 1e-10f));
        float val = lg + gmb;
        if (val > best) { best = val; bidx = v; }
    }
    sm.u.s.sv[tid] = best; sm.u.s.si[tid] = bidx;
    __syncthreads();
    for (int s = 256; s > 0; s >>= 1) {
        if (tid < s) {
            if (sm.u.s.sv[tid + s] > sm.u.s.sv[tid] ||
                (sm.u.s.sv[tid + s] == sm.u.s.sv[tid] && sm.u.s.si[tid + s] < sm.u.s.si[tid])) {
                sm.u.s.sv[tid] = sm.u.s.sv[tid + s]; sm.u.s.si[tid] = sm.u.s.si[tid + s];
            }
        }
        __syncthreads();
    }
    if (tid == 0) p.out_gen[step * BATCH + b] = (float)sm.u.s.si[0];
    __syncthreads();
}

// ---------------------------------------------------------------------------
// The megakernel — spine/branch partition pipeline
// ---------------------------------------------------------------------------
__global__ __launch_bounds__(NTHR, 2) void mega_kernel(KP p)
{
    __shared__ Smem sm;
    const int tid = threadIdx.x;
    const int bid = blockIdx.x;
    const int NSP = p.nsp;
    const int NBR = (int)gridDim.x - NSP;

    // entry: read monotonic bases BEFORE any writes
    const unsigned sbase = *(volatile unsigned*)&g_sready;
    const unsigned bbase = *(volatile unsigned*)&g_bdone;

    for (int i = bid * NTHR + tid; i < BATCH * D_DIM; i += gridDim.x * NTHR) {
        g_h1[i] = 0.f; g_c1[i] = 0.f;
        g_h2[i] = 0.f; g_c2[i] = 0.f;
        g_h3[i] = 0.f; g_c3[i] = 0.f;
        if (i < BATCH * VD) g_ctx[i] = 0.f;
    }
    full_sync();

    if (bid < NSP) {
        // ================= SPINE: recurrent LSTM chain + attention ==========
        attn_phase(p, sm, false, g_attn_scratch, -1, -1, bbase);   // ctx0
        part_sync(&g_sbar[0], &g_sbar[16], (unsigned)NSP);

        for (int t = 0; t < TDEC; t++) {
            gemm_phase<0, 16, 9, 128, 4, 1, 0>(p, sm, t, g_Gp, bid, NSP, 0);   // lstm0+cell
            part_sync(&g_sbar[0], &g_sbar[16], (unsigned)NSP);
            gemm_phase<1, 16, 8, 128, 4, 1, 0>(p, sm, t, g_Gp, bid, NSP, 0);   // lstm1+cell
            part_sync(&g_sbar[0], &g_sbar[16], (unsigned)NSP);
            gemm_phase<2, 16, 8, 128, 4, 1, 0>(p, sm, t, g_Gp, bid, NSP, 0);   // lstm2+cell
            part_sync(&g_sbar[0], &g_sbar[16], (unsigned)NSP);
            attn_phase(p, sm, true, p.out_attn + (size_t)t * BATCH * TENC,
                       t & 1, t, bbase);
            part_sync(&g_sbar[0], &g_sbar[16], (unsigned)NSP);
            if (bid == 0 && tid == 0)
                atomicExch(&g_sready, sbase + (unsigned)(t + 1));   // publish h3/ctx(t)
        }
    } else {
        // ================= BRANCH: p1 -> logits -> sample (lag 1) ===========
        const int lb = bid - NSP;
        const int sb = lb - (NBR - BATCH);        // last 64 branch blocks sample
        for (int t = 0; t < TDEC; t++) {
            if (tid == 0) {
                while (*(volatile unsigned*)&g_sready < sbase + (unsigned)(t + 1)) { }
                __threadfence();
            }
            __syncthreads();

            gemm_phase<3, 4, 20, 32, 1, 2, 16>(p, sm, t, g_Pp, lb, NBR, t & 1); // p1+hid
            part_sync(&g_bbar[0], &g_bbar[16], (unsigned)NBR);
            if (lb == 0 && tid == 0)
                atomicExch(&g_bdone, bbase + (unsigned)(t + 1));    // snapshot consumed
            gemm_phase<4, 79, LKS, 64, 2, 0, 0>(p, sm, t, g_Lp, lb, NBR, 0);    // logits
            part_sync(&g_bbar[0], &g_bbar[16], (unsigned)NBR);
            sample_phase(p, sm, t, sb);
            part_sync(&g_bbar[0], &g_bbar[16], (unsigned)NBR);
        }
    }
}

// ---------------------------------------------------------------------------
// Host launcher — single graph node
// ---------------------------------------------------------------------------
extern "C" void kernel_launch(void* const* d_in, const int* in_sizes, int n_in,
                              void* d_out, int out_size)
{
    (void)in_sizes; (void)n_in;
    KP p;
    p.inputs = (const int*)  d_in[0];
    p.keys   = (const float*)d_in[2];
    p.values = (const float*)d_in[3];
    p.ulen   = (const int*)  d_in[4];
    p.emb    = (const float*)d_in[5];
    p.w_ih0 = (const float*)d_in[6];  p.w_hh0 = (const float*)d_in[7];
    p.b_ih0 = (const float*)d_in[8];  p.b_hh0 = (const float*)d_in[9];
    p.w_ih1 = (const float*)d_in[10]; p.w_hh1 = (const float*)d_in[11];
    p.b_ih1 = (const float*)d_in[12]; p.b_hh1 = (const float*)d_in[13];
    p.w_ih2 = (const float*)d_in[14]; p.w_hh2 = (const float*)d_in[15];
    p.b_ih2 = (const float*)d_in[16]; p.b_hh2 = (const float*)d_in[17];
    p.q_w  = (const float*)d_in[18];  p.q_b  = (const float*)d_in[19];
    p.p1_w = (const float*)d_in[20];  p.p1_b = (const float*)d_in[21];
    p.p2_b = (const float*)d_in[22];

    float* out = (float*)d_out;
    const size_t L_LOG = (size_t)TDEC * BATCH * VOCAB;
    const size_t L_ATT = (size_t)TDEC * BATCH * TENC;
    const size_t TOTAL = L_LOG + L_ATT + (size_t)TDEC * BATCH;
    const bool full = (size_t)out_size >= TOTAL;

    void* vp;
    cudaGetSymbolAddress(&vp, g_attn_scratch);
    float* pAS = (float*)vp;
    cudaGetSymbolAddress(&vp, g_gen_scratch);
    float* pGS = (float*)vp;

    p.out_logits = out;
    p.out_attn   = full ? out + L_LOG         : pAS;
    p.out_gen    = full ? out + L_LOG + L_ATT : pGS;

    int dev = 0, sms = 0;
    cudaGetDevice(&dev);
    cudaDeviceGetAttribute(&sms, cudaDevAttrMultiProcessorCount, dev);
    if (sms < 64) sms = 64;

    int occ = 1;
    cudaOccupancyMaxActiveBlocksPerMultiprocessor(&occ, mega_kernel, NTHR, 0);
    if (occ < 1) occ = 1;
    if (occ > 2) occ = 2;

    int grid = sms * occ;
    int nbr = grid / 2;
    if (nbr < 128) nbr = 128;         // sampler needs 64 + headroom
    p.nsp = grid - nbr;               // attention needs >=64 spine blocks

    mega_kernel<<<grid, NTHR>>>(p);
}